// round 2
// baseline (speedup 1.0000x reference)
#include <cuda_runtime.h>
#include <math.h>

// Problem constants
#define B_SZ   32
#define T_STEPS 128
#define I_CH   16
#define N_DIM  512

// Tiling
#define TK  64            // k (output-neuron) tile per block
#define BH  16            // batches per block
#define KB  32            // reduction-chunk depth staged in smem
#define NT  256           // 4 gates * TK
#define THREADS 256

// c-state scratch (allowed: __device__ global, no allocation)
__device__ float g_c[B_SZ * I_CH * N_DIM];

struct Params {
    const float* x;
    const float* U[4];
    const float* W[4];
    const float* bias[4];
    float* out;
};

__global__ void zero_c_kernel() {
    int idx = blockIdx.x * blockDim.x + threadIdx.x;
    if (idx < B_SZ * I_CH * N_DIM) g_c[idx] = 0.0f;
}

__global__ __launch_bounds__(THREADS)
void step_kernel(Params p, int t) {
    const int kblk  = blockIdx.x;          // 0..7
    const int i_ch  = blockIdx.y;          // 0..15
    const int bgrp  = blockIdx.z;          // 0..1
    const int k0    = kblk * TK;
    const int bbase = bgrp * BH;
    const int tid   = threadIdx.x;

    extern __shared__ float smem[];
    float* h_s = smem;                      // BH * N_DIM  = 8192 floats (32 KB)
    float* w_s = smem + BH * N_DIM;         // KB * NT     = 8192 floats (32 KB); reused as s_pre

    __shared__ float u_s[4 * TK];
    __shared__ float bias_s[4 * TK];
    __shared__ float x_s[BH];

    // --- small per-block constants: U slice, bias slice, x_t ---
    {
        int g  = tid >> 6;          // gate
        int kk = tid & 63;
        u_s[tid]    = p.U[g][i_ch * N_DIM + k0 + kk];
        bias_s[tid] = p.bias[g][i_ch * N_DIM + k0 + kk];
        if (tid < BH) {
            int bg = bbase + tid;
            x_s[tid] = p.x[(bg * T_STEPS + t) * I_CH + i_ch];
        }
    }

    // --- load h (previous step's output, or zeros at t==0) into smem ---
    if (t == 0) {
        #pragma unroll
        for (int it = 0; it < 8; ++it) {
            int lin = it * THREADS + tid;   // 2048 float4 total
            reinterpret_cast<float4*>(h_s)[lin] = make_float4(0.f, 0.f, 0.f, 0.f);
        }
    } else {
        #pragma unroll
        for (int it = 0; it < 8; ++it) {
            int lin = it * THREADS + tid;
            int bl  = lin >> 7;             // local batch 0..15
            int v   = lin & 127;            // float4 index within N
            const float4* src = reinterpret_cast<const float4*>(
                p.out + (((size_t)(bbase + bl) * T_STEPS + (t - 1)) * I_CH + i_ch) * N_DIM) + v;
            reinterpret_cast<float4*>(h_s)[lin] = *src;
        }
    }

    // --- GEMM: acc[b4][c4], M=16, C=256 (4 gates x 64), K=512 ---
    float acc[4][4];
    #pragma unroll
    for (int a = 0; a < 4; ++a)
        #pragma unroll
        for (int b = 0; b < 4; ++b) acc[a][b] = 0.0f;

    const int tc = tid & 63;    // c-tile position (c = tc*4 .. tc*4+3)
    const int tb = tid >> 6;    // b-tile position (b = tb*4 .. tb*4+3)

    for (int r0 = 0; r0 < N_DIM; r0 += KB) {
        __syncthreads();  // protect w_s from prior-iter readers; first iter covers h_s
        // stage W chunk: 4 gates x KB rows x TK cols = 2048 float4
        #pragma unroll
        for (int it = 0; it < 8; ++it) {
            int lin = it * THREADS + tid;
            int g   = lin >> 9;
            int rem = lin & 511;
            int r   = rem >> 4;
            int f4  = rem & 15;
            const float4* src = reinterpret_cast<const float4*>(
                p.W[g] + ((size_t)i_ch * N_DIM + (r0 + r)) * N_DIM + k0) + f4;
            reinterpret_cast<float4*>(w_s)[r * (NT / 4) + g * (TK / 4) + f4] = *src;
        }
        __syncthreads();

        #pragma unroll 8
        for (int r = 0; r < KB; ++r) {
            float4 wv = reinterpret_cast<const float4*>(w_s + r * NT)[tc];
            float h0 = h_s[(tb * 4 + 0) * N_DIM + r0 + r];
            float h1 = h_s[(tb * 4 + 1) * N_DIM + r0 + r];
            float h2 = h_s[(tb * 4 + 2) * N_DIM + r0 + r];
            float h3 = h_s[(tb * 4 + 3) * N_DIM + r0 + r];
            acc[0][0] += h0 * wv.x; acc[0][1] += h0 * wv.y; acc[0][2] += h0 * wv.z; acc[0][3] += h0 * wv.w;
            acc[1][0] += h1 * wv.x; acc[1][1] += h1 * wv.y; acc[1][2] += h1 * wv.z; acc[1][3] += h1 * wv.w;
            acc[2][0] += h2 * wv.x; acc[2][1] += h2 * wv.y; acc[2][2] += h2 * wv.z; acc[2][3] += h2 * wv.w;
            acc[3][0] += h3 * wv.x; acc[3][1] += h3 * wv.y; acc[3][2] += h3 * wv.z; acc[3][3] += h3 * wv.w;
        }
    }

    // --- stage pre-activations so each thread can see all 4 gates at one (b,k) ---
    __syncthreads();
    float* s_pre = w_s;   // BH * NT = 4096 floats, fits in w_s
    #pragma unroll
    for (int bb = 0; bb < 4; ++bb) {
        float4 v = make_float4(acc[bb][0], acc[bb][1], acc[bb][2], acc[bb][3]);
        reinterpret_cast<float4*>(s_pre + (tb * 4 + bb) * NT)[tc] = v;
    }
    __syncthreads();

    // --- pointwise neuron update: 16 b x 64 k = 1024 elems, 4 per thread ---
    const float DT = 0.01f;
    const float A_OUT = 0.9900498337491681f;      // exp(-0.01)
    const float ONE_MINUS_A_OUT = 0.009950166250831947f;
    #pragma unroll
    for (int e = 0; e < 4; ++e) {
        int lin = e * THREADS + tid;
        int bl  = lin >> 6;          // local batch
        int kk  = lin & 63;          // k within tile

        float xb = x_s[bl];
        float pj = s_pre[bl * NT +          kk] + xb * u_s[         kk] + bias_s[         kk];
        float pi = s_pre[bl * NT +   TK +   kk] + xb * u_s[  TK +   kk] + bias_s[  TK +   kk];
        float pf = s_pre[bl * NT + 2*TK +   kk] + xb * u_s[2*TK +   kk] + bias_s[2*TK +   kk];
        float po = s_pre[bl * NT + 3*TK +   kk] + xb * u_s[3*TK +   kk] + bias_s[3*TK +   kk];

        float j  = tanhf(pj);
        float ig = 1.0f / (1.0f + expf(-pi));
        float fg = 1.0f / (1.0f + expf(-pf));
        float og = 1.0f / (1.0f + expf(-po));

        float h_old = h_s[bl * N_DIM + k0 + kk];

        float alpha_m = expf(-7.8125e-5f * j);        // exp(-(dt/tau_m)*0.5*j)
        float ro      = expf(-1.5625e-4f * ig);       // exp(-(dt/tau_adp)*0.5*i)
        float b_ad    = ro * 0.1f + (1.0f - ro) * ig;
        float Bth     = 0.04f + 1.8f * b_ad;
        float mem     = j * alpha_m + (1.0f - alpha_m) * h_old - Bth * ig * DT;
        float spike   = (mem - Bth) > 0.0f ? 1.0f : 0.0f;
        float mem_out = mem * A_OUT + ONE_MINUS_A_OUT * spike + 0.08f;

        int bg = bbase + bl;
        size_t cidx = ((size_t)bg * I_CH + i_ch) * N_DIM + k0 + kk;
        float c_new = g_c[cidx] * fg + ig * spike * mem_out;
        g_c[cidx] = c_new;
        float h_new = og * tanhf(c_new);

        p.out[(((size_t)bg * T_STEPS + t) * I_CH + i_ch) * N_DIM + k0 + kk] = h_new;
    }
}

__global__ void finalize_kernel(float* out) {
    int idx = blockIdx.x * blockDim.x + threadIdx.x;
    const int BIN = B_SZ * I_CH * N_DIM;
    if (idx >= BIN) return;
    int b   = idx / (I_CH * N_DIM);
    int rem = idx % (I_CH * N_DIM);
    float* h_fin = out + (size_t)B_SZ * T_STEPS * I_CH * N_DIM;
    float* c_fin = h_fin + BIN;
    h_fin[idx] = out[((size_t)b * T_STEPS + (T_STEPS - 1)) * I_CH * N_DIM + rem];
    c_fin[idx] = g_c[idx];
}

extern "C" void kernel_launch(void* const* d_in, const int* in_sizes, int n_in,
                              void* d_out, int out_size) {
    Params p;
    p.x = (const float*)d_in[0];
    for (int g = 0; g < 4; ++g) {
        p.U[g]    = (const float*)d_in[1 + g];   // U_j, U_i, U_f, U_o
        p.W[g]    = (const float*)d_in[5 + g];   // W_j, W_i, W_f, W_o
        p.bias[g] = (const float*)d_in[9 + g];   // b_j, b_i, b_f, b_o
    }
    p.out = (float*)d_out;

    const int smem = (BH * N_DIM + KB * NT) * (int)sizeof(float);   // 64 KB
    cudaFuncSetAttribute(step_kernel, cudaFuncAttributeMaxDynamicSharedMemorySize, smem);

    zero_c_kernel<<<(B_SZ * I_CH * N_DIM + 255) / 256, 256>>>();

    dim3 grid(N_DIM / TK, I_CH, B_SZ / BH);   // 8 x 16 x 2 = 256 blocks
    for (int t = 0; t < T_STEPS; ++t) {
        step_kernel<<<grid, THREADS, smem>>>(p, t);
    }

    finalize_kernel<<<(B_SZ * I_CH * N_DIM + 255) / 256, 256>>>(p.out);
}

// round 4
// speedup vs baseline: 2.0476x; 2.0476x over previous
#include <cuda_runtime.h>
#include <cuda_bf16.h>
#include <stdint.h>
#include <math.h>

#define B_SZ    32
#define T_STEPS 128
#define I_CH    16
#define N_DIM   512

// ---------------- scratch ----------------
// W image: 256 blobs (i,g,kt) x 256KB. Blob layout: [chunk c=0..15][hi 8KB | lo 8KB],
// each sel region: [kout=128][k2=32] bf16, 64B rows.
__device__ __align__(128) uint8_t g_wimg[256 * 262144];
__device__ float g_p[I_CH * 4 * B_SZ * N_DIM];   // preactivations [i][g][b][k]
__device__ float g_c[B_SZ * I_CH * N_DIM];

struct Params {
    const float* x;
    const float* U[4];
    const float* W[4];
    const float* bias[4];
    float* out;
};

// ---------------- helpers ----------------
__device__ __forceinline__ uint32_t smem_u32(const void* p) {
    uint32_t a;
    asm("{ .reg .u64 t; cvta.to.shared.u64 t, %1; cvt.u32.u64 %0, t; }" : "=r"(a) : "l"(p));
    return a;
}
__device__ __forceinline__ void cp16(uint32_t dst, const void* src) {
    asm volatile("cp.async.cg.shared.global [%0], [%1], 16;" :: "r"(dst), "l"(src));
}
#define CP_COMMIT()  asm volatile("cp.async.commit_group;" ::: "memory")
#define CP_WAIT(N)   asm volatile("cp.async.wait_group %0;" :: "n"(N) : "memory")

__device__ __forceinline__ void mma16816(float* d, uint32_t a0, uint32_t a1, uint32_t a2,
                                         uint32_t a3, uint32_t b0, uint32_t b1) {
    asm volatile(
        "mma.sync.aligned.m16n8k16.row.col.f32.bf16.bf16.f32 "
        "{%0,%1,%2,%3}, {%4,%5,%6,%7}, {%8,%9}, {%0,%1,%2,%3};"
        : "+f"(d[0]), "+f"(d[1]), "+f"(d[2]), "+f"(d[3])
        : "r"(a0), "r"(a1), "r"(a2), "r"(a3), "r"(b0), "r"(b1));
}
__device__ __forceinline__ uint32_t pack_bf16(float x, float y) {
    __nv_bfloat16 hx = __float2bfloat16(x), hy = __float2bfloat16(y);
    return (uint32_t)__bfloat16_as_ushort(hx) | ((uint32_t)__bfloat16_as_ushort(hy) << 16);
}

__global__ void zero_c_kernel() {
    int idx = blockIdx.x * blockDim.x + threadIdx.x;
    if (idx < B_SZ * I_CH * N_DIM) g_c[idx] = 0.0f;
}

// ---------------- prep: transpose + split + pack W ----------------
__global__ __launch_bounds__(256) void prep_kernel(Params p) {
    extern __shared__ float ts[];   // [128][132]
    int blob = blockIdx.x;
    int kt = blob & 3, g = (blob >> 2) & 3, i = blob >> 4;
    const float* W = p.W[g] + (size_t)i * N_DIM * N_DIM;
    uint8_t* dst = g_wimg + (size_t)blob * 262144;
    int m0 = kt * 128;
    int tid = threadIdx.x;

    for (int nc = 0; nc < 4; ++nc) {
        __syncthreads();
        #pragma unroll
        for (int o = 0; o < 16; ++o) {
            int e = o * 256 + tid;            // 4096 float4 loads
            int row = e >> 5, q = e & 31;
            float4 v = *reinterpret_cast<const float4*>(
                W + (size_t)(nc * 128 + row) * N_DIM + m0 + q * 4);
            float* sp = ts + row * 132 + q * 4;
            sp[0] = v.x; sp[1] = v.y; sp[2] = v.z; sp[3] = v.w;
        }
        __syncthreads();
        #pragma unroll
        for (int o = 0; o < 32; ++o) {
            int e = o * 256 + tid;            // 8192 = 128 kout x 64 kl-pairs
            int klp = e & 63, kout = e >> 6;
            int kl = klp * 2;
            float w0 = ts[kl * 132 + kout];
            float w1 = ts[(kl + 1) * 132 + kout];
            __nv_bfloat16 h0 = __float2bfloat16(w0), h1 = __float2bfloat16(w1);
            float r0 = w0 - __bfloat162float(h0), r1 = w1 - __bfloat162float(h1);
            uint32_t hv = (uint32_t)__bfloat16_as_ushort(h0) |
                          ((uint32_t)__bfloat16_as_ushort(h1) << 16);
            uint32_t lv = pack_bf16(r0, r1);
            int c = nc * 4 + (kl >> 5), k2 = kl & 31;
            *reinterpret_cast<uint32_t*>(dst + c * 16384 +        kout * 64 + k2 * 2) = hv;
            *reinterpret_cast<uint32_t*>(dst + c * 16384 + 8192 + kout * 64 + k2 * 2) = lv;
        }
    }
}

// ---------------- per-step MMA kernel ----------------
// SMEM layout (bytes): h_hi [32 x 1040] @0 | h_lo @33280 | wbuf0 @66560 (20480) | wbuf1 @87040
#define SM_HLO  33280
#define SM_WB0  66560
#define SM_WB1  87040
#define SM_TOT  107520

__global__ __launch_bounds__(256, 2) void step_mma(Params p, int t) {
    const int kt = blockIdx.x, g = blockIdx.y, i = blockIdx.z;
    extern __shared__ __align__(16) uint8_t sm[];
    const uint8_t* blob = g_wimg + (size_t)(((i * 4 + g) * 4 + kt)) * 262144;
    const int tid = threadIdx.x;
    const uint32_t smb = smem_u32(sm);

    // issue chunk 0
    {
        #pragma unroll
        for (int o = 0; o < 4; ++o) {
            int q = o * 256 + tid;
            int sel = q >> 9, r = q & 511;
            int kout = r >> 2, seg = r & 3;
            cp16(smb + SM_WB0 + sel * 10240 + kout * 80 + seg * 16,
                 blob + sel * 8192 + kout * 64 + seg * 16);
        }
        CP_COMMIT();
    }

    // stage h (split bf16) into padded smem rows
    if (t == 0) {
        for (int o = tid; o < 16640; o += 256)
            reinterpret_cast<uint32_t*>(sm)[o] = 0;
    } else {
        #pragma unroll
        for (int o = 0; o < 32; ++o) {
            int pr = o * 256 + tid;           // 8192 pairs
            int b = pr >> 8, n2 = pr & 255;
            float2 v = *reinterpret_cast<const float2*>(
                p.out + (((size_t)b * T_STEPS + (t - 1)) * I_CH + i) * N_DIM + n2 * 2);
            __nv_bfloat16 h0 = __float2bfloat16(v.x), h1 = __float2bfloat16(v.y);
            float r0 = v.x - __bfloat162float(h0), r1 = v.y - __bfloat162float(h1);
            uint32_t hv = (uint32_t)__bfloat16_as_ushort(h0) |
                          ((uint32_t)__bfloat16_as_ushort(h1) << 16);
            uint32_t lv = pack_bf16(r0, r1);
            *reinterpret_cast<uint32_t*>(sm + b * 1040 + n2 * 4)          = hv;
            *reinterpret_cast<uint32_t*>(sm + SM_HLO + b * 1040 + n2 * 4) = lv;
        }
    }
    // issue chunk 1
    {
        #pragma unroll
        for (int o = 0; o < 4; ++o) {
            int q = o * 256 + tid;
            int sel = q >> 9, r = q & 511;
            int kout = r >> 2, seg = r & 3;
            cp16(smb + SM_WB1 + sel * 10240 + kout * 80 + seg * 16,
                 blob + 16384 + sel * 8192 + kout * 64 + seg * 16);
        }
        CP_COMMIT();
    }

    const int lane = tid & 31, w = tid >> 5;
    const int gid = lane >> 2, tig = lane & 3;
    const int bh = w & 1, kc = w >> 1;     // warp tile: batch half, 32-kout chunk

    float d[4][4];
    #pragma unroll
    for (int a = 0; a < 4; ++a)
        #pragma unroll
        for (int b = 0; b < 4; ++b) d[a][b] = 0.0f;

    const int arow = (bh * 16 + gid) * 1040 + tig * 4;   // byte base into h rows

    for (int c = 0; c < 16; ++c) {
        const int buf = c & 1;
        if (c < 14) { CP_WAIT(1); } else { CP_WAIT(0); }
        __syncthreads();
        const uint8_t* wp = sm + (buf ? SM_WB1 : SM_WB0);

        #pragma unroll
        for (int ks = 0; ks < 2; ++ks) {
            const int nb = c * 64 + ks * 32;   // byte col base in h rows
            uint32_t a0 = *reinterpret_cast<const uint32_t*>(sm + arow + nb);
            uint32_t a1 = *reinterpret_cast<const uint32_t*>(sm + arow + 8 * 1040 + nb);
            uint32_t a2 = *reinterpret_cast<const uint32_t*>(sm + arow + nb + 16);
            uint32_t a3 = *reinterpret_cast<const uint32_t*>(sm + arow + 8 * 1040 + nb + 16);
            uint32_t e0 = *reinterpret_cast<const uint32_t*>(sm + SM_HLO + arow + nb);
            uint32_t e1 = *reinterpret_cast<const uint32_t*>(sm + SM_HLO + arow + 8 * 1040 + nb);
            uint32_t e2 = *reinterpret_cast<const uint32_t*>(sm + SM_HLO + arow + nb + 16);
            uint32_t e3 = *reinterpret_cast<const uint32_t*>(sm + SM_HLO + arow + 8 * 1040 + nb + 16);
            #pragma unroll
            for (int nt = 0; nt < 4; ++nt) {
                int kout = kc * 32 + nt * 8 + gid;
                int kb = ks * 32 + tig * 4;
                uint32_t b0 = *reinterpret_cast<const uint32_t*>(wp + kout * 80 + kb);
                uint32_t b1 = *reinterpret_cast<const uint32_t*>(wp + kout * 80 + kb + 16);
                uint32_t c0 = *reinterpret_cast<const uint32_t*>(wp + 10240 + kout * 80 + kb);
                uint32_t c1 = *reinterpret_cast<const uint32_t*>(wp + 10240 + kout * 80 + kb + 16);
                mma16816(d[nt], a0, a1, a2, a3, b0, b1);   // hi*hi
                mma16816(d[nt], e0, e1, e2, e3, b0, b1);   // lo*hi
                mma16816(d[nt], a0, a1, a2, a3, c0, c1);   // hi*lo
            }
        }
        __syncthreads();
        if (c + 2 < 16) {
            #pragma unroll
            for (int o = 0; o < 4; ++o) {
                int q = o * 256 + tid;
                int sel = q >> 9, r = q & 511;
                int kout = r >> 2, seg = r & 3;
                cp16(smb + (buf ? SM_WB1 : SM_WB0) + sel * 10240 + kout * 80 + seg * 16,
                     blob + (c + 2) * 16384 + sel * 8192 + kout * 64 + seg * 16);
            }
            CP_COMMIT();
        }
    }

    // store preactivations
    float* gp = g_p + ((size_t)(i * 4 + g) * 32) * 512;
    #pragma unroll
    for (int nt = 0; nt < 4; ++nt) {
        int kout = kt * 128 + kc * 32 + nt * 8 + tig * 2;
        int b = bh * 16 + gid;
        *reinterpret_cast<float2*>(gp + (size_t)b * 512 + kout)       = make_float2(d[nt][0], d[nt][1]);
        *reinterpret_cast<float2*>(gp + (size_t)(b + 8) * 512 + kout) = make_float2(d[nt][2], d[nt][3]);
    }
}

// ---------------- per-step pointwise kernel ----------------
__global__ __launch_bounds__(256) void step_point(Params p, int t) {
    int idx = blockIdx.x * 256 + threadIdx.x;   // 262144 = 16 i x 32 b x 512 k
    int k = idx & 511, b = (idx >> 9) & 31, i = idx >> 14;

    float xb = p.x[((size_t)b * T_STEPS + t) * I_CH + i];
    size_t gb = ((size_t)(i * 4) * 32 + b) * 512 + k;
    float pj = g_p[gb             ] + xb * p.U[0][i * 512 + k] + p.bias[0][i * 512 + k];
    float pi = g_p[gb + 32 * 512  ] + xb * p.U[1][i * 512 + k] + p.bias[1][i * 512 + k];
    float pf = g_p[gb + 64 * 512  ] + xb * p.U[2][i * 512 + k] + p.bias[2][i * 512 + k];
    float po = g_p[gb + 96 * 512  ] + xb * p.U[3][i * 512 + k] + p.bias[3][i * 512 + k];

    float j  = tanhf(pj);
    float ig = 1.0f / (1.0f + expf(-pi));
    float fg = 1.0f / (1.0f + expf(-pf));
    float og = 1.0f / (1.0f + expf(-po));

    float h_old = (t > 0)
        ? p.out[(((size_t)b * T_STEPS + (t - 1)) * I_CH + i) * N_DIM + k] : 0.0f;

    const float DT = 0.01f;
    const float A_OUT = 0.9900498337491681f;
    const float OMA_OUT = 0.009950166250831947f;
    // exp(x) for |x| < 2e-4: 1 + x + x^2/2 exact to fp32
    float xm = -7.8125e-5f * j;
    float alpha_m = 1.0f + xm + 0.5f * xm * xm;
    float xr = -1.5625e-4f * ig;
    float ro = 1.0f + xr + 0.5f * xr * xr;
    float b_ad = ro * 0.1f + (1.0f - ro) * ig;
    float Bth  = 0.04f + 1.8f * b_ad;
    float mem  = j * alpha_m + (1.0f - alpha_m) * h_old - Bth * ig * DT;
    float spike = (mem - Bth) > 0.0f ? 1.0f : 0.0f;
    float mem_out = mem * A_OUT + OMA_OUT * spike + 0.08f;

    size_t cidx = ((size_t)b * I_CH + i) * N_DIM + k;
    float c_new = g_c[cidx] * fg + ig * spike * mem_out;
    g_c[cidx] = c_new;
    p.out[(((size_t)b * T_STEPS + t) * I_CH + i) * N_DIM + k] = og * tanhf(c_new);
}

__global__ void finalize_kernel(float* out) {
    int idx = blockIdx.x * blockDim.x + threadIdx.x;
    const int BIN = B_SZ * I_CH * N_DIM;
    if (idx >= BIN) return;
    int b = idx / (I_CH * N_DIM);
    int rem = idx % (I_CH * N_DIM);
    float* h_fin = out + (size_t)B_SZ * T_STEPS * I_CH * N_DIM;
    float* c_fin = h_fin + BIN;
    h_fin[idx] = out[((size_t)b * T_STEPS + (T_STEPS - 1)) * I_CH * N_DIM + rem];
    c_fin[idx] = g_c[idx];
}

extern "C" void kernel_launch(void* const* d_in, const int* in_sizes, int n_in,
                              void* d_out, int out_size) {
    Params p;
    p.x = (const float*)d_in[0];
    for (int g = 0; g < 4; ++g) {
        p.U[g]    = (const float*)d_in[1 + g];
        p.W[g]    = (const float*)d_in[5 + g];
        p.bias[g] = (const float*)d_in[9 + g];
    }
    p.out = (float*)d_out;

    const int prep_smem = 128 * 132 * 4;          // 67584
    cudaFuncSetAttribute(prep_kernel, cudaFuncAttributeMaxDynamicSharedMemorySize, prep_smem);
    cudaFuncSetAttribute(step_mma,    cudaFuncAttributeMaxDynamicSharedMemorySize, SM_TOT);

    zero_c_kernel<<<(B_SZ * I_CH * N_DIM + 255) / 256, 256>>>();
    prep_kernel<<<256, 256, prep_smem>>>(p);

    dim3 grid(4, 4, I_CH);   // kt, gate, channel = 256 blocks
    for (int t = 0; t < T_STEPS; ++t) {
        step_mma<<<grid, 256, SM_TOT>>>(p, t);
        step_point<<<1024, 256>>>(p, t);
    }
    finalize_kernel<<<(B_SZ * I_CH * N_DIM + 255) / 256, 256>>>(p.out);
}

// round 5
// speedup vs baseline: 2.1416x; 1.0459x over previous
#include <cuda_runtime.h>
#include <cuda_bf16.h>
#include <stdint.h>
#include <math.h>

#define B_SZ    32
#define T_STEPS 128
#define I_CH    16
#define N_DIM   512

// ---------------- scratch ----------------
// W image: 256 blobs (i, kt) x 256KB. Blob: [chunk c=0..15][hi 8KB | lo 8KB];
// region rows r = g*32+ko (128 rows x 64B = 32 k2 bf16).
__device__ __align__(128) uint8_t g_wimg[256 * 262144];
__device__ float g_c[B_SZ * I_CH * N_DIM];

struct Params {
    const float* x;
    const float* U[4];
    const float* W[4];
    const float* bias[4];
    float* out;
};

// ---------------- helpers ----------------
__device__ __forceinline__ uint32_t smem_u32(const void* p) {
    uint32_t a;
    asm("{ .reg .u64 t; cvta.to.shared.u64 t, %1; cvt.u32.u64 %0, t; }" : "=r"(a) : "l"(p));
    return a;
}
__device__ __forceinline__ void cp16(uint32_t dst, const void* src) {
    asm volatile("cp.async.cg.shared.global [%0], [%1], 16;" :: "r"(dst), "l"(src));
}
#define CP_COMMIT()  asm volatile("cp.async.commit_group;" ::: "memory")
#define CP_WAIT(N)   asm volatile("cp.async.wait_group %0;" :: "n"(N) : "memory")

__device__ __forceinline__ void mma16816(float* d, uint32_t a0, uint32_t a1, uint32_t a2,
                                         uint32_t a3, uint32_t b0, uint32_t b1) {
    asm volatile(
        "mma.sync.aligned.m16n8k16.row.col.f32.bf16.bf16.f32 "
        "{%0,%1,%2,%3}, {%4,%5,%6,%7}, {%8,%9}, {%0,%1,%2,%3};"
        : "+f"(d[0]), "+f"(d[1]), "+f"(d[2]), "+f"(d[3])
        : "r"(a0), "r"(a1), "r"(a2), "r"(a3), "r"(b0), "r"(b1));
}
__device__ __forceinline__ uint32_t pack_bf16(float x, float y) {
    __nv_bfloat16 hx = __float2bfloat16(x), hy = __float2bfloat16(y);
    return (uint32_t)__bfloat16_as_ushort(hx) | ((uint32_t)__bfloat16_as_ushort(hy) << 16);
}

__global__ void zero_c_kernel() {
    int idx = blockIdx.x * blockDim.x + threadIdx.x;
    if (idx < B_SZ * I_CH * N_DIM) g_c[idx] = 0.0f;
}

// ---------------- prep: transpose + split + pack W (blob = i*16 + kt) ----------------
__global__ __launch_bounds__(256) void prep_kernel(Params p) {
    extern __shared__ float ts[];   // [128 n][36 pad] floats
    int blob = blockIdx.x;
    int i = blob >> 4, kt = blob & 15;
    int m0 = kt * 32;
    uint8_t* dst = g_wimg + (size_t)blob * 262144;
    int tid = threadIdx.x;

    for (int g = 0; g < 4; ++g) {
        const float* W = p.W[g] + (size_t)i * N_DIM * N_DIM;
        for (int nb = 0; nb < 4; ++nb) {
            __syncthreads();
            #pragma unroll
            for (int o = 0; o < 4; ++o) {
                int e = o * 256 + tid;          // 1024 float4 = 128 rows x 8
                int row = e >> 3, q = e & 7;
                float4 v = *reinterpret_cast<const float4*>(
                    W + (size_t)(nb * 128 + row) * N_DIM + m0 + q * 4);
                float* sp = ts + row * 36 + q * 4;
                sp[0] = v.x; sp[1] = v.y; sp[2] = v.z; sp[3] = v.w;
            }
            __syncthreads();
            #pragma unroll
            for (int o = 0; o < 8; ++o) {
                int e = o * 256 + tid;          // 2048 = 32 ko x 64 n-pairs
                int ko = e >> 6, np = e & 63;
                int n = np * 2;
                float w0 = ts[n * 36 + ko];
                float w1 = ts[(n + 1) * 36 + ko];
                __nv_bfloat16 h0 = __float2bfloat16(w0), h1 = __float2bfloat16(w1);
                uint32_t hv = (uint32_t)__bfloat16_as_ushort(h0) |
                              ((uint32_t)__bfloat16_as_ushort(h1) << 16);
                uint32_t lv = pack_bf16(w0 - __bfloat162float(h0), w1 - __bfloat162float(h1));
                int ng = nb * 128 + n;
                int c = ng >> 5, k2 = ng & 31;
                int r = g * 32 + ko;
                *reinterpret_cast<uint32_t*>(dst + c * 16384 +        r * 64 + k2 * 2) = hv;
                *reinterpret_cast<uint32_t*>(dst + c * 16384 + 8192 + r * 64 + k2 * 2) = lv;
            }
        }
    }
}

// ---------------- fused per-step kernel ----------------
// SMEM (bytes): h_hi [32 x 1040] @0 | h_lo @33280 | wbuf0 @66560 (20480) | wbuf1 @87040
// epilogue reuses wbuf0 as s_pre [32 x 132] floats (16896 B)
#define SM_HLO  33280
#define SM_WB0  66560
#define SM_WB1  87040
#define SM_TOT  107520

__global__ __launch_bounds__(256, 2) void step_fused(Params p, int t) {
    const int kt = blockIdx.x;       // 0..15: 32-wide k_out tile
    const int i  = blockIdx.y;       // 0..15: channel
    extern __shared__ __align__(16) uint8_t sm[];
    __shared__ float x_s[B_SZ];
    __shared__ float u_s[4][32], bi_s[4][32];

    const uint8_t* blob = g_wimg + (size_t)(i * 16 + kt) * 262144;
    const int tid = threadIdx.x;
    const uint32_t smb = smem_u32(sm);

    // issue chunk 0
    #pragma unroll
    for (int o = 0; o < 4; ++o) {
        int q = o * 256 + tid;
        int sel = q >> 9, r = q & 511;
        int row = r >> 2, seg = r & 3;
        cp16(smb + SM_WB0 + sel * 10240 + row * 80 + seg * 16,
             blob + sel * 8192 + row * 64 + seg * 16);
    }
    CP_COMMIT();

    if (tid < B_SZ) x_s[tid] = p.x[((size_t)tid * T_STEPS + t) * I_CH + i];
    if (tid < 128) {
        int g = tid >> 5, ko = tid & 31;
        u_s[g][ko]  = p.U[g][i * N_DIM + kt * 32 + ko];
        bi_s[g][ko] = p.bias[g][i * N_DIM + kt * 32 + ko];
    }

    // stage h (split bf16) into padded smem rows
    if (t == 0) {
        for (int o = tid; o < 16640; o += 256)
            reinterpret_cast<uint32_t*>(sm)[o] = 0;
    } else {
        #pragma unroll
        for (int o = 0; o < 32; ++o) {
            int pr = o * 256 + tid;           // 8192 pairs
            int b = pr >> 8, n2 = pr & 255;
            float2 v = *reinterpret_cast<const float2*>(
                p.out + (((size_t)b * T_STEPS + (t - 1)) * I_CH + i) * N_DIM + n2 * 2);
            __nv_bfloat16 h0 = __float2bfloat16(v.x), h1 = __float2bfloat16(v.y);
            uint32_t hv = (uint32_t)__bfloat16_as_ushort(h0) |
                          ((uint32_t)__bfloat16_as_ushort(h1) << 16);
            uint32_t lv = pack_bf16(v.x - __bfloat162float(h0), v.y - __bfloat162float(h1));
            *reinterpret_cast<uint32_t*>(sm + b * 1040 + n2 * 4)          = hv;
            *reinterpret_cast<uint32_t*>(sm + SM_HLO + b * 1040 + n2 * 4) = lv;
        }
    }
    // issue chunk 1
    #pragma unroll
    for (int o = 0; o < 4; ++o) {
        int q = o * 256 + tid;
        int sel = q >> 9, r = q & 511;
        int row = r >> 2, seg = r & 3;
        cp16(smb + SM_WB1 + sel * 10240 + row * 80 + seg * 16,
             blob + 16384 + sel * 8192 + row * 64 + seg * 16);
    }
    CP_COMMIT();

    const int lane = tid & 31, w = tid >> 5;
    const int gid = lane >> 2, tig = lane & 3;
    const int bh = w & 1, kc = w >> 1;     // warp tile: batch half, 32-col chunk

    float d[4][4];
    #pragma unroll
    for (int a = 0; a < 4; ++a)
        #pragma unroll
        for (int b = 0; b < 4; ++b) d[a][b] = 0.0f;

    const int arow = (bh * 16 + gid) * 1040 + tig * 4;

    for (int c = 0; c < 16; ++c) {
        const int buf = c & 1;
        if (c < 14) { CP_WAIT(1); } else { CP_WAIT(0); }
        __syncthreads();
        const uint8_t* wp = sm + (buf ? SM_WB1 : SM_WB0);

        #pragma unroll
        for (int ks = 0; ks < 2; ++ks) {
            const int nb = c * 64 + ks * 32;
            uint32_t a0 = *reinterpret_cast<const uint32_t*>(sm + arow + nb);
            uint32_t a1 = *reinterpret_cast<const uint32_t*>(sm + arow + 8 * 1040 + nb);
            uint32_t a2 = *reinterpret_cast<const uint32_t*>(sm + arow + nb + 16);
            uint32_t a3 = *reinterpret_cast<const uint32_t*>(sm + arow + 8 * 1040 + nb + 16);
            uint32_t e0 = *reinterpret_cast<const uint32_t*>(sm + SM_HLO + arow + nb);
            uint32_t e1 = *reinterpret_cast<const uint32_t*>(sm + SM_HLO + arow + 8 * 1040 + nb);
            uint32_t e2 = *reinterpret_cast<const uint32_t*>(sm + SM_HLO + arow + nb + 16);
            uint32_t e3 = *reinterpret_cast<const uint32_t*>(sm + SM_HLO + arow + 8 * 1040 + nb + 16);
            #pragma unroll
            for (int nt = 0; nt < 4; ++nt) {
                int col = kc * 32 + nt * 8 + gid;
                int kb = ks * 32 + tig * 4;
                uint32_t b0 = *reinterpret_cast<const uint32_t*>(wp + col * 80 + kb);
                uint32_t b1 = *reinterpret_cast<const uint32_t*>(wp + col * 80 + kb + 16);
                uint32_t c0 = *reinterpret_cast<const uint32_t*>(wp + 10240 + col * 80 + kb);
                uint32_t c1 = *reinterpret_cast<const uint32_t*>(wp + 10240 + col * 80 + kb + 16);
                mma16816(d[nt], a0, a1, a2, a3, b0, b1);   // hi*hi
                mma16816(d[nt], e0, e1, e2, e3, b0, b1);   // lo*hi
                mma16816(d[nt], a0, a1, a2, a3, c0, c1);   // hi*lo
            }
        }
        __syncthreads();
        if (c + 2 < 16) {
            #pragma unroll
            for (int o = 0; o < 4; ++o) {
                int q = o * 256 + tid;
                int sel = q >> 9, r = q & 511;
                int row = r >> 2, seg = r & 3;
                cp16(smb + (buf ? SM_WB1 : SM_WB0) + sel * 10240 + row * 80 + seg * 16,
                     blob + (c + 2) * 16384 + sel * 8192 + row * 64 + seg * 16);
            }
            CP_COMMIT();
        }
    }

    // ---- epilogue: exchange preacts via smem, fused pointwise ----
    float* s_pre = reinterpret_cast<float*>(sm + SM_WB0);   // [32][132]
    #pragma unroll
    for (int nt = 0; nt < 4; ++nt) {
        int col = kc * 32 + nt * 8 + tig * 2;
        int b = bh * 16 + gid;
        *reinterpret_cast<float2*>(s_pre + b * 132 + col)       = make_float2(d[nt][0], d[nt][1]);
        *reinterpret_cast<float2*>(s_pre + (b + 8) * 132 + col) = make_float2(d[nt][2], d[nt][3]);
    }
    __syncthreads();

    const float DT = 0.01f;
    const float A_OUT = 0.9900498337491681f;
    const float OMA_OUT = 0.009950166250831947f;
    #pragma unroll
    for (int o = 0; o < 4; ++o) {
        int lin = o * 256 + tid;              // 1024 = 32 b x 32 ko
        int b = lin >> 5, ko = lin & 31;
        int kg = kt * 32 + ko;
        float xb = x_s[b];
        float pj = s_pre[b * 132 +      ko] + xb * u_s[0][ko] + bi_s[0][ko];
        float pi = s_pre[b * 132 + 32 + ko] + xb * u_s[1][ko] + bi_s[1][ko];
        float pf = s_pre[b * 132 + 64 + ko] + xb * u_s[2][ko] + bi_s[2][ko];
        float po = s_pre[b * 132 + 96 + ko] + xb * u_s[3][ko] + bi_s[3][ko];

        float j  = tanhf(pj);
        float ig = 1.0f / (1.0f + expf(-pi));
        float fg = 1.0f / (1.0f + expf(-pf));
        float og = 1.0f / (1.0f + expf(-po));

        float h_old = (t > 0)
            ? p.out[(((size_t)b * T_STEPS + (t - 1)) * I_CH + i) * N_DIM + kg] : 0.0f;

        // exp(x), |x| < 2e-4: 1 + x + x^2/2 exact to fp32
        float xm = -7.8125e-5f * j;
        float alpha_m = 1.0f + xm + 0.5f * xm * xm;
        float xr = -1.5625e-4f * ig;
        float ro = 1.0f + xr + 0.5f * xr * xr;
        float b_ad = ro * 0.1f + (1.0f - ro) * ig;
        float Bth  = 0.04f + 1.8f * b_ad;
        float mem  = j * alpha_m + (1.0f - alpha_m) * h_old - Bth * ig * DT;
        float spike = (mem - Bth) > 0.0f ? 1.0f : 0.0f;
        float mem_out = mem * A_OUT + OMA_OUT * spike + 0.08f;

        size_t cidx = ((size_t)b * I_CH + i) * N_DIM + kg;
        float c_new = g_c[cidx] * fg + ig * spike * mem_out;
        g_c[cidx] = c_new;
        p.out[(((size_t)b * T_STEPS + t) * I_CH + i) * N_DIM + kg] = og * tanhf(c_new);
    }
}

__global__ void finalize_kernel(float* out) {
    int idx = blockIdx.x * blockDim.x + threadIdx.x;
    const int BIN = B_SZ * I_CH * N_DIM;
    if (idx >= BIN) return;
    int b = idx / (I_CH * N_DIM);
    int rem = idx % (I_CH * N_DIM);
    float* h_fin = out + (size_t)B_SZ * T_STEPS * I_CH * N_DIM;
    float* c_fin = h_fin + BIN;
    h_fin[idx] = out[((size_t)b * T_STEPS + (T_STEPS - 1)) * I_CH * N_DIM + rem];
    c_fin[idx] = g_c[idx];
}

extern "C" void kernel_launch(void* const* d_in, const int* in_sizes, int n_in,
                              void* d_out, int out_size) {
    Params p;
    p.x = (const float*)d_in[0];
    for (int g = 0; g < 4; ++g) {
        p.U[g]    = (const float*)d_in[1 + g];
        p.W[g]    = (const float*)d_in[5 + g];
        p.bias[g] = (const float*)d_in[9 + g];
    }
    p.out = (float*)d_out;

    const int prep_smem = 128 * 36 * 4;   // 18432
    cudaFuncSetAttribute(prep_kernel, cudaFuncAttributeMaxDynamicSharedMemorySize, prep_smem);
    cudaFuncSetAttribute(step_fused,  cudaFuncAttributeMaxDynamicSharedMemorySize, SM_TOT);

    zero_c_kernel<<<(B_SZ * I_CH * N_DIM + 255) / 256, 256>>>();
    prep_kernel<<<256, 256, prep_smem>>>(p);

    dim3 grid(16, I_CH);   // kt, channel = 256 blocks
    for (int t = 0; t < T_STEPS; ++t) {
        step_fused<<<grid, 256, SM_TOT>>>(p, t);
    }
    finalize_kernel<<<(B_SZ * I_CH * N_DIM + 255) / 256, 256>>>(p.out);
}

// round 6
// speedup vs baseline: 3.2202x; 1.5036x over previous
#include <cuda_runtime.h>
#include <cuda_bf16.h>
#include <stdint.h>
#include <math.h>

#define B_SZ    32
#define T_STEPS 128
#define I_CH    16
#define N_DIM   512

// ---------------- scratch ----------------
// W image: 256 blobs (i*16+kt) x 256KB; blob = 16 chunks x 16KB.
// Chunk: 1024 x 16B fragment units, q = col*8 + slot', unit = {b0,b1,c0,c1}
// (hi pair ke, hi pair ke+8, lo pair ke, lo pair ke+8) for (col, ks, tig)
// where slot' = (ks*4+tig) ^ ((col&1)<<2), ke = c*32 + ks*16 + tig*2.
__device__ __align__(128) uint8_t g_wimg[256 * 262144];
__device__ float g_c[B_SZ * I_CH * N_DIM];

struct Params {
    const float* x;
    const float* U[4];
    const float* W[4];
    const float* bias[4];
    float* out;
};

// ---------------- helpers ----------------
__device__ __forceinline__ uint32_t smem_u32(const void* p) {
    uint32_t a;
    asm("{ .reg .u64 t; cvta.to.shared.u64 t, %1; cvt.u32.u64 %0, t; }" : "=r"(a) : "l"(p));
    return a;
}
__device__ __forceinline__ void cp16(uint32_t dst, const void* src) {
    asm volatile("cp.async.cg.shared.global [%0], [%1], 16;" :: "r"(dst), "l"(src));
}
#define CP_COMMIT()  asm volatile("cp.async.commit_group;" ::: "memory")
#define CP_WAIT(N)   asm volatile("cp.async.wait_group %0;" :: "n"(N) : "memory")

__device__ __forceinline__ void mma16816(float* d, uint32_t a0, uint32_t a1, uint32_t a2,
                                         uint32_t a3, uint32_t b0, uint32_t b1) {
    asm volatile(
        "mma.sync.aligned.m16n8k16.row.col.f32.bf16.bf16.f32 "
        "{%0,%1,%2,%3}, {%4,%5,%6,%7}, {%8,%9}, {%0,%1,%2,%3};"
        : "+f"(d[0]), "+f"(d[1]), "+f"(d[2]), "+f"(d[3])
        : "r"(a0), "r"(a1), "r"(a2), "r"(a3), "r"(b0), "r"(b1));
}
__device__ __forceinline__ uint32_t pack_bf16(float x, float y) {
    __nv_bfloat16 hx = __float2bfloat16(x), hy = __float2bfloat16(y);
    return (uint32_t)__bfloat16_as_ushort(hx) | ((uint32_t)__bfloat16_as_ushort(hy) << 16);
}

__global__ void zero_c_kernel() {
    int idx = blockIdx.x * blockDim.x + threadIdx.x;
    if (idx < B_SZ * I_CH * N_DIM) g_c[idx] = 0.0f;
}

// ---------------- prep: transpose + split + fragment-pack W ----------------
__global__ __launch_bounds__(256) void prep_kernel(Params p) {
    __shared__ float ts[128 * 36];     // [n 128][ko 32 + pad]
    int blob = blockIdx.x;
    int i = blob >> 4, kt = blob & 15;
    int m0 = kt * 32;
    uint8_t* dst = g_wimg + (size_t)blob * 262144;
    int tid = threadIdx.x;

    for (int g = 0; g < 4; ++g) {
        const float* W = p.W[g] + (size_t)i * N_DIM * N_DIM;
        for (int nb = 0; nb < 4; ++nb) {
            __syncthreads();
            #pragma unroll
            for (int o = 0; o < 4; ++o) {
                int e = o * 256 + tid;            // 1024 float4 = 128 n x 8
                int row = e >> 3, q = e & 7;
                float4 v = *reinterpret_cast<const float4*>(
                    W + (size_t)(nb * 128 + row) * N_DIM + m0 + q * 4);
                float* sp = ts + row * 36 + q * 4;
                sp[0] = v.x; sp[1] = v.y; sp[2] = v.z; sp[3] = v.w;
            }
            __syncthreads();
            #pragma unroll
            for (int o = 0; o < 4; ++o) {
                int idx = o * 256 + tid;          // 1024 fragment units
                int cl = idx >> 8, r = idx & 255;
                int ko = r >> 3, slot_ = r & 7;
                int col = g * 32 + ko;
                int slot = slot_ ^ ((col & 1) << 2);
                int ks = slot >> 2, tig = slot & 3;
                int n0 = cl * 32 + ks * 16 + tig * 2;
                float w0 = ts[n0 * 36 + ko],        w1 = ts[(n0 + 1) * 36 + ko];
                float w2 = ts[(n0 + 8) * 36 + ko],  w3 = ts[(n0 + 9) * 36 + ko];
                __nv_bfloat16 h0 = __float2bfloat16(w0), h1 = __float2bfloat16(w1);
                __nv_bfloat16 h2 = __float2bfloat16(w2), h3 = __float2bfloat16(w3);
                uint4 v;
                v.x = (uint32_t)__bfloat16_as_ushort(h0) | ((uint32_t)__bfloat16_as_ushort(h1) << 16);
                v.y = (uint32_t)__bfloat16_as_ushort(h2) | ((uint32_t)__bfloat16_as_ushort(h3) << 16);
                v.z = pack_bf16(w0 - __bfloat162float(h0), w1 - __bfloat162float(h1));
                v.w = pack_bf16(w2 - __bfloat162float(h2), w3 - __bfloat162float(h3));
                *reinterpret_cast<uint4*>(
                    dst + (size_t)(nb * 4 + cl) * 16384 + (col * 8 + slot_) * 16) = v;
            }
        }
    }
}

// ---------------- fused per-step kernel ----------------
// dyn SMEM: A_hi [32KB] @0 | A_lo @32768 | wbuf x3 @65536 (16384 each)
// A unit (16B) = {a0,a1,a2,a3} at (((c*2+ks)*2+bh)*32 + lane)*16
#define SM_A_LO 32768
#define SM_WB   65536
#define SM_TOT  (65536 + 3 * 16384)   // 114688

__global__ __launch_bounds__(256, 2) void step_fused(Params p, int t) {
    const int kt = blockIdx.x;       // 0..15
    const int i  = blockIdx.y;       // 0..15
    extern __shared__ __align__(16) uint8_t sm[];
    const uint8_t* blob = g_wimg + (size_t)(i * 16 + kt) * 262144;
    const int tid = threadIdx.x;
    const uint32_t smb = smem_u32(sm);

    // issue chunks 0,1
    #pragma unroll
    for (int s = 0; s < 2; ++s) {
        #pragma unroll
        for (int o = 0; o < 4; ++o) {
            int q = o * 256 + tid;
            cp16(smb + SM_WB + s * 16384 + q * 16, blob + s * 16384 + q * 16);
        }
        CP_COMMIT();
    }

    // preload per-thread epilogue constants (ko is the same for all 4 epilogue elems)
    const int ko = tid & 31;
    const int kg = kt * 32 + ko;
    float uj = p.U[0][i * N_DIM + kg], ui = p.U[1][i * N_DIM + kg];
    float uf = p.U[2][i * N_DIM + kg], uo = p.U[3][i * N_DIM + kg];
    float bj = p.bias[0][i * N_DIM + kg], bi2 = p.bias[1][i * N_DIM + kg];
    float bf2 = p.bias[2][i * N_DIM + kg], bo2 = p.bias[3][i * N_DIM + kg];
    float xv[4];
    #pragma unroll
    for (int o = 0; o < 4; ++o) {
        int b = (tid >> 5) + o * 8;
        xv[o] = p.x[((size_t)b * T_STEPS + t) * I_CH + i];
    }

    // stage h as packed A fragments (split bf16)
    if (t == 0) {
        #pragma unroll
        for (int o = 0; o < 16; ++o)
            reinterpret_cast<uint4*>(sm)[o * 256 + tid] = make_uint4(0, 0, 0, 0);
    } else {
        #pragma unroll
        for (int o = 0; o < 32; ++o) {
            int pr = o * 256 + tid;           // 8192 pairs: b(32) x P(256)
            int b = pr >> 8, P = pr & 255;
            float2 v = *reinterpret_cast<const float2*>(
                p.out + (((size_t)b * T_STEPS + (t - 1)) * I_CH + i) * N_DIM + P * 2);
            __nv_bfloat16 h0 = __float2bfloat16(v.x), h1 = __float2bfloat16(v.y);
            uint32_t hv = (uint32_t)__bfloat16_as_ushort(h0) |
                          ((uint32_t)__bfloat16_as_ushort(h1) << 16);
            uint32_t lv = pack_bf16(v.x - __bfloat162float(h0), v.y - __bfloat162float(h1));
            int c = P >> 4, rem = P & 15, ks = rem >> 3, q3 = rem & 7;
            int tig = q3 & 3, half = q3 >> 2;
            int bh = b >> 4, rr = b & 15, gid = rr & 7, top = rr >> 3;
            uint32_t a16 = (uint32_t)((((c * 2 + ks) * 2 + bh) * 32 + gid * 4 + tig) * 16
                                      + (half * 2 + top) * 4);
            *reinterpret_cast<uint32_t*>(sm + a16)           = hv;
            *reinterpret_cast<uint32_t*>(sm + SM_A_LO + a16) = lv;
        }
    }

    const int lane = tid & 31, w = tid >> 5;
    const int gid = lane >> 2, tig = lane & 3;
    const int bh = w & 1, kc = w >> 1;

    float d[4][4];
    #pragma unroll
    for (int a = 0; a < 4; ++a)
        #pragma unroll
        for (int b = 0; b < 4; ++b) d[a][b] = 0.0f;

    for (int c = 0; c < 16; ++c) {
        if (c < 14) { CP_WAIT(1); } else { CP_WAIT(0); }
        __syncthreads();      // chunk c visible to all; also covers h staging at c==0
        if (c + 2 < 16) {     // prefetch c+2 into buf (c+2)%3 (nobody reads it now)
            uint32_t wdst = smb + SM_WB + ((c + 2) % 3) * 16384;
            const uint8_t* wsrc = blob + (size_t)(c + 2) * 16384;
            #pragma unroll
            for (int o = 0; o < 4; ++o) {
                int q = o * 256 + tid;
                cp16(wdst + q * 16, wsrc + q * 16);
            }
            CP_COMMIT();
        }
        const uint8_t* wb = sm + SM_WB + (c % 3) * 16384;

        #pragma unroll
        for (int ks = 0; ks < 2; ++ks) {
            uint32_t ab = (uint32_t)((((c * 2 + ks) * 2 + bh) * 32 + lane) * 16);
            uint4 Ah = *reinterpret_cast<const uint4*>(sm + ab);
            uint4 Al = *reinterpret_cast<const uint4*>(sm + SM_A_LO + ab);
            #pragma unroll
            for (int nt = 0; nt < 4; ++nt) {
                int col = kc * 32 + nt * 8 + gid;
                int slot_ = (ks * 4 + tig) ^ ((col & 1) << 2);
                uint4 B = *reinterpret_cast<const uint4*>(wb + (col * 8 + slot_) * 16);
                mma16816(d[nt], Ah.x, Ah.y, Ah.z, Ah.w, B.x, B.y);  // hi*hi
                mma16816(d[nt], Al.x, Al.y, Al.z, Al.w, B.x, B.y);  // lo*hi
                mma16816(d[nt], Ah.x, Ah.y, Ah.z, Ah.w, B.z, B.w);  // hi*lo
            }
        }
    }

    // ---- epilogue ----
    __syncthreads();          // all MMAs done before reusing wbuf as s_pre
    float* s_pre = reinterpret_cast<float*>(sm + SM_WB);   // [32][132]
    #pragma unroll
    for (int nt = 0; nt < 4; ++nt) {
        int col = kc * 32 + nt * 8 + tig * 2;
        int b = bh * 16 + gid;
        *reinterpret_cast<float2*>(s_pre + b * 132 + col)       = make_float2(d[nt][0], d[nt][1]);
        *reinterpret_cast<float2*>(s_pre + (b + 8) * 132 + col) = make_float2(d[nt][2], d[nt][3]);
    }
    __syncthreads();

    const float DT = 0.01f;
    const float A_OUT = 0.9900498337491681f;
    const float OMA_OUT = 0.009950166250831947f;
    #pragma unroll
    for (int o = 0; o < 4; ++o) {
        int b = (tid >> 5) + o * 8;
        float xb = xv[o];
        float pj = s_pre[b * 132 +      ko] + xb * uj + bj;
        float pi = s_pre[b * 132 + 32 + ko] + xb * ui + bi2;
        float pf = s_pre[b * 132 + 64 + ko] + xb * uf + bf2;
        float po = s_pre[b * 132 + 96 + ko] + xb * uo + bo2;

        float j  = tanhf(pj);
        float ig = 1.0f / (1.0f + expf(-pi));
        float fg = 1.0f / (1.0f + expf(-pf));
        float og = 1.0f / (1.0f + expf(-po));

        float h_old = (t > 0)
            ? p.out[(((size_t)b * T_STEPS + (t - 1)) * I_CH + i) * N_DIM + kg] : 0.0f;

        // exp(x), |x| < 2e-4: 1 + x + x^2/2 exact to fp32
        float xm = -7.8125e-5f * j;
        float alpha_m = 1.0f + xm + 0.5f * xm * xm;
        float xr = -1.5625e-4f * ig;
        float ro = 1.0f + xr + 0.5f * xr * xr;
        float b_ad = ro * 0.1f + (1.0f - ro) * ig;
        float Bth  = 0.04f + 1.8f * b_ad;
        float mem  = j * alpha_m + (1.0f - alpha_m) * h_old - Bth * ig * DT;
        float spike = (mem - Bth) > 0.0f ? 1.0f : 0.0f;
        float mem_out = mem * A_OUT + OMA_OUT * spike + 0.08f;

        size_t cidx = ((size_t)b * I_CH + i) * N_DIM + kg;
        float c_new = g_c[cidx] * fg + ig * spike * mem_out;
        g_c[cidx] = c_new;
        p.out[(((size_t)b * T_STEPS + t) * I_CH + i) * N_DIM + kg] = og * tanhf(c_new);
    }
}

__global__ void finalize_kernel(float* out) {
    int idx = blockIdx.x * blockDim.x + threadIdx.x;
    const int BIN = B_SZ * I_CH * N_DIM;
    if (idx >= BIN) return;
    int b = idx / (I_CH * N_DIM);
    int rem = idx % (I_CH * N_DIM);
    float* h_fin = out + (size_t)B_SZ * T_STEPS * I_CH * N_DIM;
    float* c_fin = h_fin + BIN;
    h_fin[idx] = out[((size_t)b * T_STEPS + (T_STEPS - 1)) * I_CH * N_DIM + rem];
    c_fin[idx] = g_c[idx];
}

extern "C" void kernel_launch(void* const* d_in, const int* in_sizes, int n_in,
                              void* d_out, int out_size) {
    Params p;
    p.x = (const float*)d_in[0];
    for (int g = 0; g < 4; ++g) {
        p.U[g]    = (const float*)d_in[1 + g];
        p.W[g]    = (const float*)d_in[5 + g];
        p.bias[g] = (const float*)d_in[9 + g];
    }
    p.out = (float*)d_out;

    cudaFuncSetAttribute(step_fused, cudaFuncAttributeMaxDynamicSharedMemorySize, SM_TOT);

    zero_c_kernel<<<(B_SZ * I_CH * N_DIM + 255) / 256, 256>>>();
    prep_kernel<<<256, 256>>>(p);

    dim3 grid(16, I_CH);   // kt, channel = 256 blocks
    for (int t = 0; t < T_STEPS; ++t) {
        step_fused<<<grid, 256, SM_TOT>>>(p, t);
    }
    finalize_kernel<<<(B_SZ * I_CH * N_DIM + 255) / 256, 256>>>(p.out);
}

// round 7
// speedup vs baseline: 3.3455x; 1.0389x over previous
#include <cuda_runtime.h>
#include <cuda_bf16.h>
#include <stdint.h>
#include <math.h>

#define B_SZ    32
#define T_STEPS 128
#define I_CH    16
#define N_DIM   512

// ---------------- scratch ----------------
// W image: 128 blobs (i*8+kt) x 512KB; blob = 16 chunks (n-groups of 32) x 32KB.
// Chunk: 2048 x 16B units, q = col*8 + slot_, col = g*64+ko (0..255),
// slot_ = (ks*4+tig) ^ ((col&1)<<2); unit = {hi pair n0, hi pair n0+8, lo pair n0, lo pair n0+8}.
__device__ __align__(128) uint8_t g_wimg[128 * 524288];
__device__ unsigned int g_bar;

struct Params {
    const float* x;
    const float* U[4];
    const float* W[4];
    const float* bias[4];
    float* out;
};

// ---------------- helpers ----------------
__device__ __forceinline__ uint32_t smem_u32(const void* p) {
    uint32_t a;
    asm("{ .reg .u64 t; cvta.to.shared.u64 t, %1; cvt.u32.u64 %0, t; }" : "=r"(a) : "l"(p));
    return a;
}
__device__ __forceinline__ void cp16(uint32_t dst, const void* src) {
    asm volatile("cp.async.cg.shared.global [%0], [%1], 16;" :: "r"(dst), "l"(src));
}
#define CP_COMMIT()  asm volatile("cp.async.commit_group;" ::: "memory")
#define CP_WAIT(N)   asm volatile("cp.async.wait_group %0;" :: "n"(N) : "memory")

__device__ __forceinline__ void mma16816(float* d, uint32_t a0, uint32_t a1, uint32_t a2,
                                         uint32_t a3, uint32_t b0, uint32_t b1) {
    asm volatile(
        "mma.sync.aligned.m16n8k16.row.col.f32.bf16.bf16.f32 "
        "{%0,%1,%2,%3}, {%4,%5,%6,%7}, {%8,%9}, {%0,%1,%2,%3};"
        : "+f"(d[0]), "+f"(d[1]), "+f"(d[2]), "+f"(d[3])
        : "r"(a0), "r"(a1), "r"(a2), "r"(a3), "r"(b0), "r"(b1));
}
__device__ __forceinline__ uint32_t pack_bf16(float x, float y) {
    __nv_bfloat16 hx = __float2bfloat16(x), hy = __float2bfloat16(y);
    return (uint32_t)__bfloat16_as_ushort(hx) | ((uint32_t)__bfloat16_as_ushort(hy) << 16);
}

// ---------------- prep: transpose + split + fragment-pack W; reset barrier ----------------
__global__ __launch_bounds__(256) void prep_kernel(Params p) {
    __shared__ float ts[128 * 68];     // [n 128][ko 64 + pad]
    int blob = blockIdx.x;             // 0..127
    int i = blob >> 3, kt = blob & 7;
    if (blob == 0 && threadIdx.x == 0) g_bar = 0;
    int m0 = kt * 64;
    uint8_t* dst = g_wimg + (size_t)blob * 524288;
    int tid = threadIdx.x;

    for (int g = 0; g < 4; ++g) {
        const float* W = p.W[g] + (size_t)i * N_DIM * N_DIM;
        for (int nb = 0; nb < 4; ++nb) {
            __syncthreads();
            #pragma unroll
            for (int o = 0; o < 8; ++o) {
                int e = o * 256 + tid;            // 2048 float4 = 128 n x 16
                int row = e >> 4, q = e & 15;
                float4 v = *reinterpret_cast<const float4*>(
                    W + (size_t)(nb * 128 + row) * N_DIM + m0 + q * 4);
                float* sp = ts + row * 68 + q * 4;
                sp[0] = v.x; sp[1] = v.y; sp[2] = v.z; sp[3] = v.w;
            }
            __syncthreads();
            #pragma unroll
            for (int o = 0; o < 8; ++o) {
                int idx = o * 256 + tid;          // 2048 units
                int cl = idx >> 9, r = idx & 511;
                int ko = r >> 3, slot_ = r & 7;
                int col = g * 64 + ko;
                int slot = slot_ ^ ((col & 1) << 2);
                int ks = slot >> 2, tg = slot & 3;
                int n0 = cl * 32 + ks * 16 + tg * 2;
                float w0 = ts[n0 * 68 + ko],       w1 = ts[(n0 + 1) * 68 + ko];
                float w2 = ts[(n0 + 8) * 68 + ko], w3 = ts[(n0 + 9) * 68 + ko];
                __nv_bfloat16 h0 = __float2bfloat16(w0), h1 = __float2bfloat16(w1);
                __nv_bfloat16 h2 = __float2bfloat16(w2), h3 = __float2bfloat16(w3);
                uint4 v;
                v.x = (uint32_t)__bfloat16_as_ushort(h0) | ((uint32_t)__bfloat16_as_ushort(h1) << 16);
                v.y = (uint32_t)__bfloat16_as_ushort(h2) | ((uint32_t)__bfloat16_as_ushort(h3) << 16);
                v.z = pack_bf16(w0 - __bfloat162float(h0), w1 - __bfloat162float(h1));
                v.w = pack_bf16(w2 - __bfloat162float(h2), w3 - __bfloat162float(h3));
                *reinterpret_cast<uint4*>(
                    dst + (size_t)(nb * 4 + cl) * 32768 + (col * 8 + slot_) * 16) = v;
            }
        }
    }
}

// ---------------- persistent kernel ----------------
// dyn SMEM: A_hi @0 (32K) | A_lo @32768 | h32 @65536 (8K) | wbuf x3 @73728 (32K each) | s_pre @172032 (33280)
#define SM_A_LO 32768
#define SM_H32  65536
#define SM_WB   73728
#define SM_PRE  172032
#define SM_TOT  205312

__global__ __launch_bounds__(512, 1) void persist_kernel(Params p) {
    const int kt = blockIdx.x;   // 0..7 (64-wide k_out tile)
    const int i  = blockIdx.y;   // 0..15
    extern __shared__ __align__(16) uint8_t sm[];
    const uint8_t* blob = g_wimg + (size_t)(i * 8 + kt) * 524288;
    const int tid = threadIdx.x;
    const uint32_t smb = smem_u32(sm);

    const int lane = tid & 31, w = tid >> 5;
    const int gid = lane >> 2, tig = lane & 3;
    const int bh = w & 1, kc = w >> 1;          // kc 0..7

    // epilogue ownership: (b = eb0 + o*8, kg) fixed over all t
    const int ko = tid & 63;
    const int kg = kt * 64 + ko;
    const int eb0 = tid >> 6;                   // 0..7
    const float uj = p.U[0][i * N_DIM + kg], ui = p.U[1][i * N_DIM + kg];
    const float uf = p.U[2][i * N_DIM + kg], uo = p.U[3][i * N_DIM + kg];
    const float bj = p.bias[0][i * N_DIM + kg], bi2 = p.bias[1][i * N_DIM + kg];
    const float bf2 = p.bias[2][i * N_DIM + kg], bo2 = p.bias[3][i * N_DIM + kg];
    float creg[4] = {0.f, 0.f, 0.f, 0.f};

    float* h32   = reinterpret_cast<float*>(sm + SM_H32);
    float* s_pre = reinterpret_cast<float*>(sm + SM_PRE);   // [32][260]

    // prime W pipeline: chunks 0,1
    #pragma unroll
    for (int s = 0; s < 2; ++s) {
        #pragma unroll
        for (int o = 0; o < 4; ++o) {
            int q = o * 512 + tid;
            cp16(smb + SM_WB + s * 32768 + q * 16, blob + (size_t)s * 32768 + q * 16);
        }
        CP_COMMIT();
    }

    for (int t = 0; t < T_STEPS; ++t) {
        float xv[4];
        #pragma unroll
        for (int o = 0; o < 4; ++o)
            xv[o] = __ldg(&p.x[((size_t)(eb0 + o * 8) * T_STEPS + t) * I_CH + i]);

        // ---- stage A (h split bf16) + h32 ----
        if (t == 0) {
            #pragma unroll
            for (int o = 0; o < 9; ++o)          // 4608 uint4 = A(4096) + h32(512)
                reinterpret_cast<uint4*>(sm)[o * 512 + tid] = make_uint4(0, 0, 0, 0);
        } else {
            #pragma unroll
            for (int o = 0; o < 16; ++o) {
                int pr = o * 512 + tid;           // 8192 pairs: b(32) x P(256)
                int b = pr >> 8, P = pr & 255;
                float2 v = __ldcg(reinterpret_cast<const float2*>(
                    p.out + (((size_t)b * T_STEPS + (t - 1)) * I_CH + i) * N_DIM + P * 2));
                __nv_bfloat16 h0 = __float2bfloat16(v.x), h1 = __float2bfloat16(v.y);
                uint32_t hv = (uint32_t)__bfloat16_as_ushort(h0) |
                              ((uint32_t)__bfloat16_as_ushort(h1) << 16);
                uint32_t lv = pack_bf16(v.x - __bfloat162float(h0), v.y - __bfloat162float(h1));
                int c = P >> 4, rem = P & 15, ks = rem >> 3, q3 = rem & 7;
                int tg = q3 & 3, half = q3 >> 2;
                int bhh = b >> 4, rr = b & 15, gg = rr & 7, top = rr >> 3;
                uint32_t a16 = (uint32_t)((((c * 2 + ks) * 2 + bhh) * 32 + gg * 4 + tg) * 16
                                          + (half * 2 + top) * 4);
                *reinterpret_cast<uint32_t*>(sm + a16)           = hv;
                *reinterpret_cast<uint32_t*>(sm + SM_A_LO + a16) = lv;
                int Pl = P - kt * 32;
                if (Pl >= 0 && Pl < 32)
                    *reinterpret_cast<float2*>(h32 + b * 64 + Pl * 2) = v;
            }
        }

        // ---- mainloop over 16 n-chunks ----
        float d[4][4];
        #pragma unroll
        for (int a = 0; a < 4; ++a)
            #pragma unroll
            for (int b = 0; b < 4; ++b) d[a][b] = 0.0f;

        for (int c = 0; c < 16; ++c) {
            if (c < 14) { CP_WAIT(1); } else { CP_WAIT(0); }
            __syncthreads();
            if (c + 2 < 16) {
                uint32_t wdst = smb + SM_WB + ((c + 2) % 3) * 32768;
                const uint8_t* wsrc = blob + (size_t)(c + 2) * 32768;
                #pragma unroll
                for (int o = 0; o < 4; ++o) {
                    int q = o * 512 + tid;
                    cp16(wdst + q * 16, wsrc + q * 16);
                }
                CP_COMMIT();
            }
            const uint8_t* wb = sm + SM_WB + (c % 3) * 32768;
            #pragma unroll
            for (int ks = 0; ks < 2; ++ks) {
                uint32_t ab = (uint32_t)((((c * 2 + ks) * 2 + bh) * 32 + lane) * 16);
                uint4 Ah = *reinterpret_cast<const uint4*>(sm + ab);
                uint4 Al = *reinterpret_cast<const uint4*>(sm + SM_A_LO + ab);
                #pragma unroll
                for (int nt = 0; nt < 4; ++nt) {
                    int col = kc * 32 + nt * 8 + gid;
                    int slot_ = (ks * 4 + tig) ^ ((col & 1) << 2);
                    uint4 B = *reinterpret_cast<const uint4*>(wb + (col * 8 + slot_) * 16);
                    mma16816(d[nt], Ah.x, Ah.y, Ah.z, Ah.w, B.x, B.y);  // hi*hi
                    mma16816(d[nt], Al.x, Al.y, Al.z, Al.w, B.x, B.y);  // lo*hi
                    mma16816(d[nt], Ah.x, Ah.y, Ah.z, Ah.w, B.z, B.w);  // hi*lo
                }
            }
        }
        __syncthreads();   // all wbuf reads done

        // prefetch next step's chunk 0 (W constant over t)
        if (t + 1 < T_STEPS) {
            #pragma unroll
            for (int o = 0; o < 4; ++o) {
                int q = o * 512 + tid;
                cp16(smb + SM_WB + q * 16, blob + q * 16);
            }
            CP_COMMIT();
        }

        // exchange preacts
        #pragma unroll
        for (int nt = 0; nt < 4; ++nt) {
            int col = kc * 32 + nt * 8 + tig * 2;
            int b = bh * 16 + gid;
            *reinterpret_cast<float2*>(s_pre + b * 260 + col)       = make_float2(d[nt][0], d[nt][1]);
            *reinterpret_cast<float2*>(s_pre + (b + 8) * 260 + col) = make_float2(d[nt][2], d[nt][3]);
        }

        // prefetch next step's chunk 1
        if (t + 1 < T_STEPS) {
            #pragma unroll
            for (int o = 0; o < 4; ++o) {
                int q = o * 512 + tid;
                cp16(smb + SM_WB + 32768 + q * 16, blob + 32768 + q * 16);
            }
            CP_COMMIT();
        }
        __syncthreads();

        // ---- fused pointwise epilogue ----
        const float DT = 0.01f;
        const float A_OUT = 0.9900498337491681f;
        const float OMA_OUT = 0.009950166250831947f;
        #pragma unroll
        for (int o = 0; o < 4; ++o) {
            int b = eb0 + o * 8;
            float xb = xv[o];
            float pj = s_pre[b * 260 +       ko] + xb * uj + bj;
            float pi = s_pre[b * 260 +  64 + ko] + xb * ui + bi2;
            float pf = s_pre[b * 260 + 128 + ko] + xb * uf + bf2;
            float po = s_pre[b * 260 + 192 + ko] + xb * uo + bo2;

            float j  = tanhf(pj);
            float ig = 1.0f / (1.0f + expf(-pi));
            float fg = 1.0f / (1.0f + expf(-pf));
            float og = 1.0f / (1.0f + expf(-po));

            float h_old = h32[b * 64 + ko];

            // exp(x), |x| < 2e-4: 1 + x + x^2/2 exact to fp32
            float xm = -7.8125e-5f * j;
            float alpha_m = 1.0f + xm + 0.5f * xm * xm;
            float xr = -1.5625e-4f * ig;
            float ro = 1.0f + xr + 0.5f * xr * xr;
            float b_ad = ro * 0.1f + (1.0f - ro) * ig;
            float Bth  = 0.04f + 1.8f * b_ad;
            float mem  = j * alpha_m + (1.0f - alpha_m) * h_old - Bth * ig * DT;
            float spike = (mem - Bth) > 0.0f ? 1.0f : 0.0f;
            float mem_out = mem * A_OUT + OMA_OUT * spike + 0.08f;

            float c_new = creg[o] * fg + ig * spike * mem_out;
            creg[o] = c_new;
            float h_new = og * tanhf(c_new);
            p.out[(((size_t)b * T_STEPS + t) * I_CH + i) * N_DIM + kg] = h_new;
            if (t == T_STEPS - 1) {
                float* h_fin = p.out + (size_t)B_SZ * T_STEPS * I_CH * N_DIM;
                float* c_fin = h_fin + B_SZ * I_CH * N_DIM;
                size_t fidx = ((size_t)b * I_CH + i) * N_DIM + kg;
                h_fin[fidx] = h_new;
                c_fin[fidx] = c_new;
            }
        }

        // ---- grid barrier (all 128 CTAs co-resident: 1 CTA/SM by smem) ----
        if (t + 1 < T_STEPS) {
            __threadfence();
            __syncthreads();
            if (tid == 0) {
                atomicAdd(&g_bar, 1u);
                unsigned target = (unsigned)(t + 1) * 128u;
                unsigned v;
                do {
                    asm volatile("ld.acquire.gpu.u32 %0, [%1];"
                                 : "=r"(v) : "l"(&g_bar) : "memory");
                } while (v < target);
            }
            __syncthreads();
        }
    }
}

extern "C" void kernel_launch(void* const* d_in, const int* in_sizes, int n_in,
                              void* d_out, int out_size) {
    Params p;
    p.x = (const float*)d_in[0];
    for (int g = 0; g < 4; ++g) {
        p.U[g]    = (const float*)d_in[1 + g];
        p.W[g]    = (const float*)d_in[5 + g];
        p.bias[g] = (const float*)d_in[9 + g];
    }
    p.out = (float*)d_out;

    cudaFuncSetAttribute(persist_kernel, cudaFuncAttributeMaxDynamicSharedMemorySize, SM_TOT);

    prep_kernel<<<128, 256>>>(p);                 // also resets g_bar each replay
    dim3 grid(8, I_CH);                           // 128 blocks, 1/SM guaranteed
    persist_kernel<<<grid, 512, SM_TOT>>>(p);
}

// round 8
// speedup vs baseline: 4.4423x; 1.3279x over previous
#include <cuda_runtime.h>
#include <cuda_fp16.h>
#include <stdint.h>
#include <math.h>

#define B_SZ    32
#define T_STEPS 128
#define I_CH    16
#define N_DIM   512

// ---------------- scratch ----------------
// W image (fp16, single plane): 128 blobs (i*8+kt) x 256KB; blob = 8 chunks (64 n) x 32KB.
// Chunk: 2048 x 16B units at addr16 = (((kc*2+p)*4+ks)*32 + lane);
// unit = {b0(col_a),b1(col_a),b0(col_b),b1(col_b)}, col_a = kc*32+p*16+gid, col_b = col_a+8,
// k-slice = c*64+ks*16, b0 = W[col][k0+2tig..+1], b1 = W[col][k0+2tig+8..+9].
__device__ __align__(128) uint8_t g_wimg[128 * 262144];
__device__ unsigned int g_bar;

struct Params {
    const float* x;
    const float* U[4];
    const float* W[4];
    const float* bias[4];
    float* out;
};

// ---------------- helpers ----------------
__device__ __forceinline__ uint32_t smem_u32(const void* p) {
    uint32_t a;
    asm("{ .reg .u64 t; cvta.to.shared.u64 t, %1; cvt.u32.u64 %0, t; }" : "=r"(a) : "l"(p));
    return a;
}
__device__ __forceinline__ void cp16(uint32_t dst, const void* src) {
    asm volatile("cp.async.cg.shared.global [%0], [%1], 16;" :: "r"(dst), "l"(src));
}
#define CP_COMMIT()  asm volatile("cp.async.commit_group;" ::: "memory")
#define CP_WAIT(N)   asm volatile("cp.async.wait_group %0;" :: "n"(N) : "memory")

__device__ __forceinline__ void mma16816(float* d, uint32_t a0, uint32_t a1, uint32_t a2,
                                         uint32_t a3, uint32_t b0, uint32_t b1) {
    asm volatile(
        "mma.sync.aligned.m16n8k16.row.col.f32.f16.f16.f32 "
        "{%0,%1,%2,%3}, {%4,%5,%6,%7}, {%8,%9}, {%0,%1,%2,%3};"
        : "+f"(d[0]), "+f"(d[1]), "+f"(d[2]), "+f"(d[3])
        : "r"(a0), "r"(a1), "r"(a2), "r"(a3), "r"(b0), "r"(b1));
}
__device__ __forceinline__ uint32_t packh(float x, float y) {
    __half hx = __float2half_rn(x), hy = __float2half_rn(y);
    return (uint32_t)__half_as_ushort(hx) | ((uint32_t)__half_as_ushort(hy) << 16);
}

// ---------------- prep: transpose + fp16-pack W; reset barrier ----------------
__global__ __launch_bounds__(256) void prep_kernel(Params p) {
    __shared__ float ts[128 * 68];     // [n 128][ko 64 + pad]
    int blob = blockIdx.x;             // 0..127
    int i = blob >> 3, kt = blob & 7;
    if (blob == 0 && threadIdx.x == 0) g_bar = 0;
    int m0 = kt * 64;
    uint8_t* dst = g_wimg + (size_t)blob * 262144;
    int tid = threadIdx.x;

    for (int g = 0; g < 4; ++g) {
        const float* W = p.W[g] + (size_t)i * N_DIM * N_DIM;
        for (int nb = 0; nb < 4; ++nb) {            // 128-n groups
            __syncthreads();
            #pragma unroll
            for (int o = 0; o < 8; ++o) {
                int e = o * 256 + tid;              // 2048 float4 = 128 n x 16
                int row = e >> 4, q = e & 15;
                float4 v = *reinterpret_cast<const float4*>(
                    W + (size_t)(nb * 128 + row) * N_DIM + m0 + q * 4);
                float* sp = ts + row * 68 + q * 4;
                sp[0] = v.x; sp[1] = v.y; sp[2] = v.z; sp[3] = v.w;
            }
            __syncthreads();
            #pragma unroll
            for (int o = 0; o < 4; ++o) {
                int idx = o * 256 + tid;            // 1024 units per (g, nb)
                int cl  = idx >> 9;                 // local chunk (64 n each)
                int r   = idx & 511;
                int kcl = (r >> 8) & 1, pp = (r >> 7) & 1;
                int ks  = (r >> 5) & 3, lane = r & 31;
                int gid = lane >> 2, tig = lane & 3;
                int ko_a = kcl * 32 + pp * 16 + gid;
                int ko_b = ko_a + 8;
                int n0 = cl * 64 + ks * 16 + tig * 2;
                uint4 u;
                u.x = packh(ts[n0 * 68 + ko_a],       ts[(n0 + 1) * 68 + ko_a]);
                u.y = packh(ts[(n0 + 8) * 68 + ko_a], ts[(n0 + 9) * 68 + ko_a]);
                u.z = packh(ts[n0 * 68 + ko_b],       ts[(n0 + 1) * 68 + ko_b]);
                u.w = packh(ts[(n0 + 8) * 68 + ko_b], ts[(n0 + 9) * 68 + ko_b]);
                int kc = 2 * g + kcl;
                int chunk = nb * 2 + cl;
                *reinterpret_cast<uint4*>(
                    dst + (size_t)chunk * 32768
                        + ((((kc * 2 + pp) * 4 + ks) * 32 + lane) << 4)) = u;
            }
        }
    }
}

// ---------------- persistent kernel ----------------
// dyn SMEM: A_hi @0 (32K) | A_lo @32768 | h32 @65536 (8K) | wbuf x3 @73728 (32K each) | s_pre @172032
// A unit (16B) = {a0,a1,a2,a3} at (((c*4+ks)*2+bh)*32 + lane)*16
#define SM_A_LO 32768
#define SM_H32  65536
#define SM_WB   73728
#define SM_PRE  172032
#define SM_TOT  205312

__global__ __launch_bounds__(512, 1) void persist_kernel(Params p) {
    const int kt = blockIdx.x;   // 0..7 (64-wide k_out tile)
    const int i  = blockIdx.y;   // 0..15
    extern __shared__ __align__(16) uint8_t sm[];
    const uint8_t* blob = g_wimg + (size_t)(i * 8 + kt) * 262144;
    const int tid = threadIdx.x;
    const uint32_t smb = smem_u32(sm);

    const int lane = tid & 31, w = tid >> 5;
    const int bh = w & 1, kc = w >> 1;          // kc 0..7

    // epilogue ownership
    const int ko = tid & 63;
    const int kg = kt * 64 + ko;
    const int eb0 = tid >> 6;                   // 0..7
    const float uj = p.U[0][i * N_DIM + kg], ui = p.U[1][i * N_DIM + kg];
    const float uf = p.U[2][i * N_DIM + kg], uo = p.U[3][i * N_DIM + kg];
    const float bj = p.bias[0][i * N_DIM + kg], bi2 = p.bias[1][i * N_DIM + kg];
    const float bf2 = p.bias[2][i * N_DIM + kg], bo2 = p.bias[3][i * N_DIM + kg];
    float creg[4] = {0.f, 0.f, 0.f, 0.f};

    float* h32   = reinterpret_cast<float*>(sm + SM_H32);
    float* s_pre = reinterpret_cast<float*>(sm + SM_PRE);   // [32][260]

    // prime W pipeline: chunks 0,1
    #pragma unroll
    for (int s = 0; s < 2; ++s) {
        #pragma unroll
        for (int o = 0; o < 4; ++o) {
            int q = o * 512 + tid;
            cp16(smb + SM_WB + s * 32768 + q * 16, blob + (size_t)s * 32768 + q * 16);
        }
        CP_COMMIT();
    }

    for (int t = 0; t < T_STEPS; ++t) {
        float xv[4];
        #pragma unroll
        for (int o = 0; o < 4; ++o)
            xv[o] = __ldg(&p.x[((size_t)(eb0 + o * 8) * T_STEPS + t) * I_CH + i]);

        // ---- stage A (h split fp16) + h32 ----
        if (t == 0) {
            #pragma unroll
            for (int o = 0; o < 9; ++o)
                reinterpret_cast<uint4*>(sm)[o * 512 + tid] = make_uint4(0, 0, 0, 0);
        } else {
            #pragma unroll
            for (int o = 0; o < 16; ++o) {
                int pr = o * 512 + tid;           // 8192 pairs: b(32) x P(256)
                int b = pr >> 8, P = pr & 255;
                float2 v = __ldcg(reinterpret_cast<const float2*>(
                    p.out + (((size_t)b * T_STEPS + (t - 1)) * I_CH + i) * N_DIM + P * 2));
                __half h0 = __float2half_rn(v.x), h1 = __float2half_rn(v.y);
                uint32_t hv = (uint32_t)__half_as_ushort(h0) |
                              ((uint32_t)__half_as_ushort(h1) << 16);
                uint32_t lv = packh(v.x - __half2float(h0), v.y - __half2float(h1));
                int c = P >> 5;
                int ks = (P >> 3) & 3, half = (P >> 2) & 1, tg = P & 3;
                int bhh = b >> 4, rr = b & 15, gg = rr & 7, top = rr >> 3;
                uint32_t a16 = (uint32_t)((((c * 4 + ks) * 2 + bhh) * 32 + gg * 4 + tg) * 16
                                          + (half * 2 + top) * 4);
                *reinterpret_cast<uint32_t*>(sm + a16)           = hv;
                *reinterpret_cast<uint32_t*>(sm + SM_A_LO + a16) = lv;
                int Pl = P - kt * 32;
                if (Pl >= 0 && Pl < 32)
                    *reinterpret_cast<float2*>(h32 + b * 64 + Pl * 2) = v;
            }
        }

        // ---- mainloop over 8 n-chunks of 64 ----
        float d[4][4];
        #pragma unroll
        for (int a = 0; a < 4; ++a)
            #pragma unroll
            for (int b = 0; b < 4; ++b) d[a][b] = 0.0f;

        for (int c = 0; c < 8; ++c) {
            if (c < 6) { CP_WAIT(1); } else { CP_WAIT(0); }
            __syncthreads();
            if (c + 2 < 8) {
                uint32_t wdst = smb + SM_WB + ((c + 2) % 3) * 32768;
                const uint8_t* wsrc = blob + (size_t)(c + 2) * 32768;
                #pragma unroll
                for (int o = 0; o < 4; ++o) {
                    int q = o * 512 + tid;
                    cp16(wdst + q * 16, wsrc + q * 16);
                }
                CP_COMMIT();
            }
            const uint8_t* wb = sm + SM_WB + (c % 3) * 32768;
            #pragma unroll
            for (int ks = 0; ks < 4; ++ks) {
                uint32_t ab = (uint32_t)((((c * 4 + ks) * 2 + bh) * 32 + lane) * 16);
                uint4 Ah = *reinterpret_cast<const uint4*>(sm + ab);
                uint4 Al = *reinterpret_cast<const uint4*>(sm + SM_A_LO + ab);
                #pragma unroll
                for (int pp = 0; pp < 2; ++pp) {
                    uint4 B = *reinterpret_cast<const uint4*>(
                        wb + ((((kc * 2 + pp) * 4 + ks) * 32 + lane) << 4));
                    mma16816(d[pp * 2 + 0], Ah.x, Ah.y, Ah.z, Ah.w, B.x, B.y);
                    mma16816(d[pp * 2 + 0], Al.x, Al.y, Al.z, Al.w, B.x, B.y);
                    mma16816(d[pp * 2 + 1], Ah.x, Ah.y, Ah.z, Ah.w, B.z, B.w);
                    mma16816(d[pp * 2 + 1], Al.x, Al.y, Al.z, Al.w, B.z, B.w);
                }
            }
        }
        __syncthreads();   // all wbuf reads done

        // prefetch next step's chunk 0 (W constant over t)
        if (t + 1 < T_STEPS) {
            #pragma unroll
            for (int o = 0; o < 4; ++o) {
                int q = o * 512 + tid;
                cp16(smb + SM_WB + q * 16, blob + q * 16);
            }
            CP_COMMIT();
        }

        // exchange preacts: d[nt] -> col = kc*32 + nt*8 + gid (nt = pp*2 + ab-half)
        const int gid = lane >> 2, tig = lane & 3;
        #pragma unroll
        for (int nt = 0; nt < 4; ++nt) {
            int col = kc * 32 + ((nt >> 1) * 16 + (nt & 1) * 8) + tig * 2;
            int b = bh * 16 + gid;
            // NOTE: d[nt] columns: nt0:+0, nt1:+8, nt2:+16, nt3:+24 — same linear map:
            col = kc * 32 + nt * 8 + tig * 2;
            *reinterpret_cast<float2*>(s_pre + b * 260 + col)       = make_float2(d[nt][0], d[nt][1]);
            *reinterpret_cast<float2*>(s_pre + (b + 8) * 260 + col) = make_float2(d[nt][2], d[nt][3]);
        }

        // prefetch next step's chunk 1
        if (t + 1 < T_STEPS) {
            #pragma unroll
            for (int o = 0; o < 4; ++o) {
                int q = o * 512 + tid;
                cp16(smb + SM_WB + 32768 + q * 16, blob + 32768 + q * 16);
            }
            CP_COMMIT();
        }
        __syncthreads();

        // ---- fused pointwise epilogue ----
        const float DT = 0.01f;
        const float A_OUT = 0.9900498337491681f;
        const float OMA_OUT = 0.009950166250831947f;
        #pragma unroll
        for (int o = 0; o < 4; ++o) {
            int b = eb0 + o * 8;
            float xb = xv[o];
            float pj = s_pre[b * 260 +       ko] + xb * uj + bj;
            float pi = s_pre[b * 260 +  64 + ko] + xb * ui + bi2;
            float pf = s_pre[b * 260 + 128 + ko] + xb * uf + bf2;
            float po = s_pre[b * 260 + 192 + ko] + xb * uo + bo2;

            float j  = tanhf(pj);
            float ig = 1.0f / (1.0f + expf(-pi));
            float fg = 1.0f / (1.0f + expf(-pf));
            float og = 1.0f / (1.0f + expf(-po));

            float h_old = h32[b * 64 + ko];

            float xm = -7.8125e-5f * j;
            float alpha_m = 1.0f + xm + 0.5f * xm * xm;
            float xr = -1.5625e-4f * ig;
            float ro = 1.0f + xr + 0.5f * xr * xr;
            float b_ad = ro * 0.1f + (1.0f - ro) * ig;
            float Bth  = 0.04f + 1.8f * b_ad;
            float mem  = j * alpha_m + (1.0f - alpha_m) * h_old - Bth * ig * DT;
            float spike = (mem - Bth) > 0.0f ? 1.0f : 0.0f;
            float mem_out = mem * A_OUT + OMA_OUT * spike + 0.08f;

            float c_new = creg[o] * fg + ig * spike * mem_out;
            creg[o] = c_new;
            float h_new = og * tanhf(c_new);
            p.out[(((size_t)b * T_STEPS + t) * I_CH + i) * N_DIM + kg] = h_new;
            if (t == T_STEPS - 1) {
                float* h_fin = p.out + (size_t)B_SZ * T_STEPS * I_CH * N_DIM;
                float* c_fin = h_fin + B_SZ * I_CH * N_DIM;
                size_t fidx = ((size_t)b * I_CH + i) * N_DIM + kg;
                h_fin[fidx] = h_new;
                c_fin[fidx] = c_new;
            }
        }

        // ---- grid barrier (128 CTAs, 1/SM by smem) ----
        if (t + 1 < T_STEPS) {
            __threadfence();
            __syncthreads();
            if (tid == 0) {
                atomicAdd(&g_bar, 1u);
                unsigned target = (unsigned)(t + 1) * 128u;
                unsigned v;
                do {
                    asm volatile("ld.acquire.gpu.u32 %0, [%1];"
                                 : "=r"(v) : "l"(&g_bar) : "memory");
                } while (v < target);
            }
            __syncthreads();
        }
    }
}

extern "C" void kernel_launch(void* const* d_in, const int* in_sizes, int n_in,
                              void* d_out, int out_size) {
    Params p;
    p.x = (const float*)d_in[0];
    for (int g = 0; g < 4; ++g) {
        p.U[g]    = (const float*)d_in[1 + g];
        p.W[g]    = (const float*)d_in[5 + g];
        p.bias[g] = (const float*)d_in[9 + g];
    }
    p.out = (float*)d_out;

    cudaFuncSetAttribute(persist_kernel, cudaFuncAttributeMaxDynamicSharedMemorySize, SM_TOT);

    prep_kernel<<<128, 256>>>(p);                 // also resets g_bar each replay
    dim3 grid(8, I_CH);                           // 128 blocks
    persist_kernel<<<grid, 512, SM_TOT>>>(p);
}

// round 9
// speedup vs baseline: 4.6384x; 1.0441x over previous
#include <cuda_runtime.h>
#include <cuda_fp16.h>
#include <stdint.h>
#include <math.h>

#define B_SZ    32
#define T_STEPS 128
#define I_CH    16
#define N_DIM   512

// ---------------- scratch ----------------
// W image (fp16): 128 blobs (i*8+kt) x 256KB; blob = 8 chunks (64 n) x 32KB.
// addr(c,ks,pp) per warp: blob + kc*4096 + lane*16 + c*32768 + pp*2048 + ks*512
// unit = {b0(col_a),b1(col_a),b0(col_b),b1(col_b)}, col_a = kc*32+pp*16+gid, col_b = col_a+8.
__device__ __align__(128) uint8_t g_wimg[128 * 262144];
__device__ unsigned int g_bar;

struct Params {
    const float* x;
    const float* U[4];
    const float* W[4];
    const float* bias[4];
    float* out;
};

// ---------------- helpers ----------------
__device__ __forceinline__ void mma16816(float* d, uint32_t a0, uint32_t a1, uint32_t a2,
                                         uint32_t a3, uint32_t b0, uint32_t b1) {
    asm volatile(
        "mma.sync.aligned.m16n8k16.row.col.f32.f16.f16.f32 "
        "{%0,%1,%2,%3}, {%4,%5,%6,%7}, {%8,%9}, {%0,%1,%2,%3};"
        : "+f"(d[0]), "+f"(d[1]), "+f"(d[2]), "+f"(d[3])
        : "r"(a0), "r"(a1), "r"(a2), "r"(a3), "r"(b0), "r"(b1));
}
__device__ __forceinline__ uint32_t packh(float x, float y) {
    __half hx = __float2half_rn(x), hy = __float2half_rn(y);
    return (uint32_t)__half_as_ushort(hx) | ((uint32_t)__half_as_ushort(hy) << 16);
}

// ---------------- prep: transpose + fp16-pack W; reset barrier ----------------
__global__ __launch_bounds__(256) void prep_kernel(Params p) {
    __shared__ float ts[128 * 68];     // [n 128][ko 64 + pad]
    int blob = blockIdx.x;             // 0..127
    int i = blob >> 3, kt = blob & 7;
    if (blob == 0 && threadIdx.x == 0) g_bar = 0;
    int m0 = kt * 64;
    uint8_t* dst = g_wimg + (size_t)blob * 262144;
    int tid = threadIdx.x;

    for (int g = 0; g < 4; ++g) {
        const float* W = p.W[g] + (size_t)i * N_DIM * N_DIM;
        for (int nb = 0; nb < 4; ++nb) {            // 128-n groups
            __syncthreads();
            #pragma unroll
            for (int o = 0; o < 8; ++o) {
                int e = o * 256 + tid;              // 2048 float4 = 128 n x 16
                int row = e >> 4, q = e & 15;
                float4 v = *reinterpret_cast<const float4*>(
                    W + (size_t)(nb * 128 + row) * N_DIM + m0 + q * 4);
                float* sp = ts + row * 68 + q * 4;
                sp[0] = v.x; sp[1] = v.y; sp[2] = v.z; sp[3] = v.w;
            }
            __syncthreads();
            #pragma unroll
            for (int o = 0; o < 4; ++o) {
                int idx = o * 256 + tid;            // 1024 units per (g, nb)
                int cl  = idx >> 9;                 // local chunk (64 n each)
                int r   = idx & 511;
                int kcl = (r >> 8) & 1, pp = (r >> 7) & 1;
                int ks  = (r >> 5) & 3, lane = r & 31;
                int gid = lane >> 2, tig = lane & 3;
                int ko_a = kcl * 32 + pp * 16 + gid;
                int ko_b = ko_a + 8;
                int n0 = cl * 64 + ks * 16 + tig * 2;
                uint4 u;
                u.x = packh(ts[n0 * 68 + ko_a],       ts[(n0 + 1) * 68 + ko_a]);
                u.y = packh(ts[(n0 + 8) * 68 + ko_a], ts[(n0 + 9) * 68 + ko_a]);
                u.z = packh(ts[n0 * 68 + ko_b],       ts[(n0 + 1) * 68 + ko_b]);
                u.w = packh(ts[(n0 + 8) * 68 + ko_b], ts[(n0 + 9) * 68 + ko_b]);
                int kc = 2 * g + kcl;
                int chunk = nb * 2 + cl;
                *reinterpret_cast<uint4*>(
                    dst + (size_t)chunk * 32768
                        + ((((kc * 2 + pp) * 4 + ks) * 32 + lane) << 4)) = u;
            }
        }
    }
}

// ---------------- persistent kernel ----------------
// dyn SMEM: A_hi @0 (32K) | A_lo @32768 | h32 @65536 (8K) | s_pre @73728 (33280)
// A unit (16B) = {a0,a1,a2,a3} at (((c*4+ks)*2+bh)*32 + lane)*16
#define SM_A_LO 32768
#define SM_H32  65536
#define SM_PRE  73728
#define SM_TOT  107008

__global__ __launch_bounds__(512, 1) void persist_kernel(Params p) {
    const int kt = blockIdx.x;   // 0..7 (64-wide k_out tile)
    const int i  = blockIdx.y;   // 0..15
    extern __shared__ __align__(16) uint8_t sm[];
    const uint8_t* blob = g_wimg + (size_t)(i * 8 + kt) * 262144;
    const int tid = threadIdx.x;

    const int lane = tid & 31, w = tid >> 5;
    const int bh = w & 1, kc = w >> 1;          // kc 0..7
    const int gid = lane >> 2, tig = lane & 3;

    // per-warp B base: addr(c,ks,pp) = wp + c*32768 + pp*2048 + ks*512
    const uint8_t* wp = blob + kc * 4096 + lane * 16;

    // epilogue ownership
    const int ko = tid & 63;
    const int kg = kt * 64 + ko;
    const int eb0 = tid >> 6;                   // 0..7
    const float uj = p.U[0][i * N_DIM + kg], ui = p.U[1][i * N_DIM + kg];
    const float uf = p.U[2][i * N_DIM + kg], uo = p.U[3][i * N_DIM + kg];
    const float bj = p.bias[0][i * N_DIM + kg], bi2 = p.bias[1][i * N_DIM + kg];
    const float bf2 = p.bias[2][i * N_DIM + kg], bo2 = p.bias[3][i * N_DIM + kg];
    float creg[4] = {0.f, 0.f, 0.f, 0.f};

    float* h32   = reinterpret_cast<float*>(sm + SM_H32);
    float* s_pre = reinterpret_cast<float*>(sm + SM_PRE);   // [32][260]

    for (int t = 0; t < T_STEPS; ++t) {
        float xv[4];
        #pragma unroll
        for (int o = 0; o < 4; ++o)
            xv[o] = __ldg(&p.x[((size_t)(eb0 + o * 8) * T_STEPS + t) * I_CH + i]);

        // ---- stage A (h split fp16) + h32 ----
        if (t == 0) {
            #pragma unroll
            for (int o = 0; o < 9; ++o)
                reinterpret_cast<uint4*>(sm)[o * 512 + tid] = make_uint4(0, 0, 0, 0);
        } else {
            #pragma unroll
            for (int o = 0; o < 16; ++o) {
                int pr = o * 512 + tid;           // 8192 pairs: b(32) x P(256)
                int b = pr >> 8, P = pr & 255;
                float2 v = __ldcg(reinterpret_cast<const float2*>(
                    p.out + (((size_t)b * T_STEPS + (t - 1)) * I_CH + i) * N_DIM + P * 2));
                __half h0 = __float2half_rn(v.x), h1 = __float2half_rn(v.y);
                uint32_t hv = (uint32_t)__half_as_ushort(h0) |
                              ((uint32_t)__half_as_ushort(h1) << 16);
                uint32_t lv = packh(v.x - __half2float(h0), v.y - __half2float(h1));
                int c = P >> 5;
                int ks = (P >> 3) & 3, half = (P >> 2) & 1, tg = P & 3;
                int bhh = b >> 4, rr = b & 15, gg = rr & 7, top = rr >> 3;
                uint32_t a16 = (uint32_t)((((c * 4 + ks) * 2 + bhh) * 32 + gg * 4 + tg) * 16
                                          + (half * 2 + top) * 4);
                *reinterpret_cast<uint32_t*>(sm + a16)           = hv;
                *reinterpret_cast<uint32_t*>(sm + SM_A_LO + a16) = lv;
                int Pl = P - kt * 32;
                if (Pl >= 0 && Pl < 32)
                    *reinterpret_cast<float2*>(h32 + b * 64 + Pl * 2) = v;
            }
        }
        __syncthreads();

        // ---- mainloop: 32 flat (c,ks) iterations, B from L2 via LDG, 1-ahead prefetch ----
        float d[4][4];
        #pragma unroll
        for (int a = 0; a < 4; ++a)
            #pragma unroll
            for (int b = 0; b < 4; ++b) d[a][b] = 0.0f;

        uint4 Bn0 = __ldg(reinterpret_cast<const uint4*>(wp));
        uint4 Bn1 = __ldg(reinterpret_cast<const uint4*>(wp + 2048));

        #pragma unroll 4
        for (int it = 0; it < 32; ++it) {
            const int c = it >> 2, ks = it & 3;
            uint4 B0 = Bn0, B1 = Bn1;
            if (it + 1 < 32) {
                const int it2 = it + 1;
                const uint8_t* q = wp + (it2 >> 2) * 32768 + (it2 & 3) * 512;
                Bn0 = __ldg(reinterpret_cast<const uint4*>(q));
                Bn1 = __ldg(reinterpret_cast<const uint4*>(q + 2048));
            }
            uint32_t ab = (uint32_t)((((c * 4 + ks) * 2 + bh) * 32 + lane) * 16);
            uint4 Ah = *reinterpret_cast<const uint4*>(sm + ab);
            uint4 Al = *reinterpret_cast<const uint4*>(sm + SM_A_LO + ab);
            mma16816(d[0], Ah.x, Ah.y, Ah.z, Ah.w, B0.x, B0.y);
            mma16816(d[0], Al.x, Al.y, Al.z, Al.w, B0.x, B0.y);
            mma16816(d[1], Ah.x, Ah.y, Ah.z, Ah.w, B0.z, B0.w);
            mma16816(d[1], Al.x, Al.y, Al.z, Al.w, B0.z, B0.w);
            mma16816(d[2], Ah.x, Ah.y, Ah.z, Ah.w, B1.x, B1.y);
            mma16816(d[2], Al.x, Al.y, Al.z, Al.w, B1.x, B1.y);
            mma16816(d[3], Ah.x, Ah.y, Ah.z, Ah.w, B1.z, B1.w);
            mma16816(d[3], Al.x, Al.y, Al.z, Al.w, B1.z, B1.w);
        }
        __syncthreads();   // A reads done before s_pre (aliases nothing) & next-step staging

        // exchange preacts: d[nt] -> col = kc*32 + nt*8 (nt: 0=+0, 1=+8, 2=+16, 3=+24)
        #pragma unroll
        for (int nt = 0; nt < 4; ++nt) {
            int col = kc * 32 + nt * 8 + tig * 2;
            int b = bh * 16 + gid;
            *reinterpret_cast<float2*>(s_pre + b * 260 + col)       = make_float2(d[nt][0], d[nt][1]);
            *reinterpret_cast<float2*>(s_pre + (b + 8) * 260 + col) = make_float2(d[nt][2], d[nt][3]);
        }
        __syncthreads();

        // ---- fused pointwise epilogue ----
        const float DT = 0.01f;
        const float A_OUT = 0.9900498337491681f;
        const float OMA_OUT = 0.009950166250831947f;
        #pragma unroll
        for (int o = 0; o < 4; ++o) {
            int b = eb0 + o * 8;
            float xb = xv[o];
            float pj = s_pre[b * 260 +       ko] + xb * uj + bj;
            float pi = s_pre[b * 260 +  64 + ko] + xb * ui + bi2;
            float pf = s_pre[b * 260 + 128 + ko] + xb * uf + bf2;
            float po = s_pre[b * 260 + 192 + ko] + xb * uo + bo2;

            float j  = tanhf(pj);
            float ig = 1.0f / (1.0f + expf(-pi));
            float fg = 1.0f / (1.0f + expf(-pf));
            float og = 1.0f / (1.0f + expf(-po));

            float h_old = h32[b * 64 + ko];

            float xm = -7.8125e-5f * j;
            float alpha_m = 1.0f + xm + 0.5f * xm * xm;
            float xr = -1.5625e-4f * ig;
            float ro = 1.0f + xr + 0.5f * xr * xr;
            float b_ad = ro * 0.1f + (1.0f - ro) * ig;
            float Bth  = 0.04f + 1.8f * b_ad;
            float mem  = j * alpha_m + (1.0f - alpha_m) * h_old - Bth * ig * DT;
            float spike = (mem - Bth) > 0.0f ? 1.0f : 0.0f;
            float mem_out = mem * A_OUT + OMA_OUT * spike + 0.08f;

            float c_new = creg[o] * fg + ig * spike * mem_out;
            creg[o] = c_new;
            float h_new = og * tanhf(c_new);
            p.out[(((size_t)b * T_STEPS + t) * I_CH + i) * N_DIM + kg] = h_new;
            if (t == T_STEPS - 1) {
                float* h_fin = p.out + (size_t)B_SZ * T_STEPS * I_CH * N_DIM;
                float* c_fin = h_fin + B_SZ * I_CH * N_DIM;
                size_t fidx = ((size_t)b * I_CH + i) * N_DIM + kg;
                h_fin[fidx] = h_new;
                c_fin[fidx] = c_new;
            }
        }

        // ---- grid barrier (128 CTAs, all co-resident) ----
        if (t + 1 < T_STEPS) {
            __threadfence();
            __syncthreads();
            if (tid == 0) {
                atomicAdd(&g_bar, 1u);
                unsigned target = (unsigned)(t + 1) * 128u;
                unsigned v;
                do {
                    asm volatile("ld.acquire.gpu.u32 %0, [%1];"
                                 : "=r"(v) : "l"(&g_bar) : "memory");
                } while (v < target);
            }
            __syncthreads();
        }
    }
}

extern "C" void kernel_launch(void* const* d_in, const int* in_sizes, int n_in,
                              void* d_out, int out_size) {
    Params p;
    p.x = (const float*)d_in[0];
    for (int g = 0; g < 4; ++g) {
        p.U[g]    = (const float*)d_in[1 + g];
        p.W[g]    = (const float*)d_in[5 + g];
        p.bias[g] = (const float*)d_in[9 + g];
    }
    p.out = (float*)d_out;

    cudaFuncSetAttribute(persist_kernel, cudaFuncAttributeMaxDynamicSharedMemorySize, SM_TOT);

    prep_kernel<<<128, 256>>>(p);                 // also resets g_bar each replay
    dim3 grid(8, I_CH);                           // 128 blocks
    persist_kernel<<<grid, 512, SM_TOT>>>(p);
}